// round 7
// baseline (speedup 1.0000x reference)
#include <cuda_runtime.h>
#include <cuda_fp16.h>
#include <cstdint>
#include <math.h>

#define B_ 64
#define S_ 2048
#define H_ 1024
#define M_ (B_*S_)
#define NTILES 8          // H_/128 N-blocks
#define KT 32             // k floats per tile
#define K_ITERS (H_/KT)   // 32
#define RS 80             // smem row stride bytes (padded, conflict-free)
#define STAGE (128*RS)    // 10240 B per operand stage

__device__ float g_dp[B_ * H_];
__device__ float g_part[NTILES * M_];
__device__ int   g_mask_mode;

__device__ __forceinline__ uint32_t smem_u32(const void* p) {
    uint32_t a;
    asm("{ .reg .u64 t; cvta.to.shared.u64 t, %1; cvt.u32.u64 %0, t; }" : "=r"(a) : "l"(p));
    return a;
}
__device__ __forceinline__ uint32_t pack_h2(float lo, float hi) {
    __half2 h = __floats2half2_rn(lo, hi);
    return *(uint32_t*)&h;
}
__device__ __forceinline__ void ldsm_x4(uint32_t r[4], uint32_t addr) {
    asm volatile("ldmatrix.sync.aligned.m8n8.x4.shared.b16 {%0,%1,%2,%3}, [%4];"
                 : "=r"(r[0]), "=r"(r[1]), "=r"(r[2]), "=r"(r[3]) : "r"(addr));
}
// fp16-accumulate HMMA: D,C are 2 packed f16x2 regs.
__device__ __forceinline__ void mma_f16acc(uint32_t d[2], const uint32_t a[4],
                                           uint32_t b0, uint32_t b1) {
    asm volatile(
        "mma.sync.aligned.m16n8k16.row.col.f16.f16.f16.f16 "
        "{%0,%1}, {%2,%3,%4,%5}, {%6,%7}, {%0,%1};"
        : "+r"(d[0]), "+r"(d[1])
        : "r"(a[0]), "r"(a[1]), "r"(a[2]), "r"(a[3]), "r"(b0), "r"(b1));
}
__device__ __forceinline__ float fast_tanh(float x) {
    float y; asm("tanh.approx.f32 %0, %1;" : "=f"(y) : "f"(x)); return y;
}

// ---------------------------------------------------------------------------
__global__ void sniff_mask_kernel(const unsigned int* __restrict__ m) {
    unsigned w = m[0];
    int mode;
    if (w == 0x01010101u)      mode = 0;  // uint8/bool
    else if (w == 0x3F800000u) mode = 2;  // float32
    else                       mode = 1;  // int32
    g_mask_mode = mode;
}

// ---------------------------------------------------------------------------
__global__ void dec_proj_kernel(const float* __restrict__ dec,
                                const float* __restrict__ Wdec) {
    int wid  = (blockIdx.x * blockDim.x + threadIdx.x) >> 5;
    int lane = threadIdx.x & 31;
    int o  = wid >> 4;
    int b0 = (wid & 15) * 4;
    const float* wr = Wdec + (size_t)o * H_;
    const float* d0 = dec + (size_t)(b0 + 0) * H_;
    const float* d1 = dec + (size_t)(b0 + 1) * H_;
    const float* d2 = dec + (size_t)(b0 + 2) * H_;
    const float* d3 = dec + (size_t)(b0 + 3) * H_;
    float a0 = 0.f, a1 = 0.f, a2 = 0.f, a3 = 0.f;
    #pragma unroll 4
    for (int h = lane; h < H_; h += 32) {
        float w = wr[h];
        a0 = fmaf(w, d0[h], a0);
        a1 = fmaf(w, d1[h], a1);
        a2 = fmaf(w, d2[h], a2);
        a3 = fmaf(w, d3[h], a3);
    }
    #pragma unroll
    for (int off = 16; off; off >>= 1) {
        a0 += __shfl_down_sync(0xffffffffu, a0, off);
        a1 += __shfl_down_sync(0xffffffffu, a1, off);
        a2 += __shfl_down_sync(0xffffffffu, a2, off);
        a3 += __shfl_down_sync(0xffffffffu, a3, off);
    }
    if (lane == 0) {
        g_dp[(size_t)(b0 + 0) * H_ + o] = a0;
        g_dp[(size_t)(b0 + 1) * H_ + o] = a1;
        g_dp[(size_t)(b0 + 2) * H_ + o] = a2;
        g_dp[(size_t)(b0 + 3) * H_ + o] = a3;
    }
}

// ---------------------------------------------------------------------------
// Fused fp16 MMA GEMM (enc @ W_enc^T) with fp16 accumulators promoted to an
// fp32 register shadow every 4 k-tiles (K-chunk 128), + tanh epilogue.
// Block 128(M)x128(N), k-tile 32, double-buffered smem, ldmatrix fragments.
// 8 warps: 2(M) x 4(N); warp tile 64x32.
// ---------------------------------------------------------------------------
__global__ void __launch_bounds__(256, 1)
fused_score_kernel(const float* __restrict__ enc,
                   const float* __restrict__ Wenc,
                   const float* __restrict__ v) {
    __shared__ __align__(16) char smA[2][STAGE];
    __shared__ __align__(16) char smB[2][STAGE];
    __shared__ float dp_sh[128];
    __shared__ float v_sh[128];
    __shared__ float part_sh[4][128];

    const int tid   = threadIdx.x;
    const int lane  = tid & 31;
    const int warp  = tid >> 5;
    const int warpM = warp & 1;
    const int warpN = warp >> 1;
    const int g = lane >> 2;
    const int t = lane & 3;

    const int nBase = blockIdx.x * 128;
    const int mBase = blockIdx.y * 128;
    const int b     = mBase >> 11;

    if (tid < 128) {
        dp_sh[tid] = g_dp[(size_t)b * H_ + nBase + tid];
        v_sh[tid]  = v[nBase + tid];
    }

    const uint32_t smA0 = smem_u32(&smA[0][0]);
    const uint32_t smB0 = smem_u32(&smB[0][0]);

    float    accf[4][4][4];   // fp32 shadow
    uint32_t hacc[4][4][2];   // fp16x2 running accumulators
    #pragma unroll
    for (int mi = 0; mi < 4; mi++)
        #pragma unroll
        for (int ni = 0; ni < 4; ni++) {
            #pragma unroll
            for (int c = 0; c < 4; c++) accf[mi][ni][c] = 0.f;
            hacc[mi][ni][0] = 0u; hacc[mi][ni][1] = 0u;
        }

    // global staging: thread owns half a row (16 floats) of A and of B per ktile
    const int rowG  = tid >> 1;          // 0..127
    const int halfG = tid & 1;           // 0/1 -> k offset 16 floats
    const float* Ag = enc  + (size_t)(mBase + rowG) * H_ + halfG * 16;
    const float* Bg = Wenc + (size_t)(nBase + rowG) * H_ + halfG * 16;
    const uint32_t stBase = rowG * RS + halfG * 32;   // 16 floats -> 32 bytes f16

    float4 ar[4], br[4];

#define LOADG(KTI) {                                                        \
    const size_t ko = (size_t)(KTI) * KT;                                   \
    _Pragma("unroll")                                                       \
    for (int i = 0; i < 4; i++) {                                           \
        ar[i] = *(const float4*)(Ag + ko + i * 4);                          \
        br[i] = *(const float4*)(Bg + ko + i * 4);                          \
    } }

#define STORES(BUF) {                                                      \
    uint32_t ha[8], hb[8];                                                  \
    _Pragma("unroll")                                                       \
    for (int i = 0; i < 4; i++) {                                           \
        ha[2*i]   = pack_h2(ar[i].x, ar[i].y);                              \
        ha[2*i+1] = pack_h2(ar[i].z, ar[i].w);                              \
        hb[2*i]   = pack_h2(br[i].x, br[i].y);                              \
        hb[2*i+1] = pack_h2(br[i].z, br[i].w);                              \
    }                                                                       \
    uint32_t da = smA0 + (BUF) * STAGE + stBase;                            \
    uint32_t db = smB0 + (BUF) * STAGE + stBase;                            \
    asm volatile("st.shared.v4.b32 [%0], {%1,%2,%3,%4};" ::                 \
        "r"(da), "r"(ha[0]), "r"(ha[1]), "r"(ha[2]), "r"(ha[3]));           \
    asm volatile("st.shared.v4.b32 [%0], {%1,%2,%3,%4};" ::                 \
        "r"(da + 16), "r"(ha[4]), "r"(ha[5]), "r"(ha[6]), "r"(ha[7]));      \
    asm volatile("st.shared.v4.b32 [%0], {%1,%2,%3,%4};" ::                 \
        "r"(db), "r"(hb[0]), "r"(hb[1]), "r"(hb[2]), "r"(hb[3]));           \
    asm volatile("st.shared.v4.b32 [%0], {%1,%2,%3,%4};" ::                 \
        "r"(db + 16), "r"(hb[4]), "r"(hb[5]), "r"(hb[6]), "r"(hb[7]));      \
    }

    // ldmatrix per-lane address components
    const int aRow = warpM * 64 + (lane & 7) + ((lane >> 3) & 1) * 8;
    const int aCol = ((lane >> 4) & 1) * 16;
    const int bRow = warpN * 32 + (lane >> 4) * 8 + (lane & 7);
    const int bCol = ((lane >> 3) & 1) * 16;

#define COMPUTE(BUF) {                                                     \
    const uint32_t Ab = smA0 + (BUF) * STAGE;                               \
    const uint32_t Bb = smB0 + (BUF) * STAGE;                               \
    _Pragma("unroll")                                                       \
    for (int ks = 0; ks < 2; ks++) {                                        \
        uint32_t af[4][4], bf[2][4];                                        \
        _Pragma("unroll")                                                   \
        for (int mi = 0; mi < 4; mi++)                                      \
            ldsm_x4(af[mi], Ab + (aRow + mi * 16) * RS + ks * 32 + aCol);   \
        _Pragma("unroll")                                                   \
        for (int nj = 0; nj < 2; nj++)                                      \
            ldsm_x4(bf[nj], Bb + (bRow + nj * 16) * RS + ks * 32 + bCol);   \
        _Pragma("unroll")                                                   \
        for (int mi = 0; mi < 4; mi++) {                                    \
            _Pragma("unroll")                                               \
            for (int nj = 0; nj < 2; nj++) {                                \
                mma_f16acc(hacc[mi][2*nj],   af[mi], bf[nj][0], bf[nj][1]); \
                mma_f16acc(hacc[mi][2*nj+1], af[mi], bf[nj][2], bf[nj][3]); \
            }                                                               \
        }                                                                   \
    } }

    // promote fp16 accumulators into fp32 shadow and reset them
#define PROMOTE() {                                                        \
    _Pragma("unroll")                                                       \
    for (int mi = 0; mi < 4; mi++) {                                        \
        _Pragma("unroll")                                                   \
        for (int ni = 0; ni < 4; ni++) {                                    \
            float2 f0 = __half22float2(*(__half2*)&hacc[mi][ni][0]);        \
            float2 f1 = __half22float2(*(__half2*)&hacc[mi][ni][1]);        \
            accf[mi][ni][0] += f0.x;  accf[mi][ni][1] += f0.y;              \
            accf[mi][ni][2] += f1.x;  accf[mi][ni][3] += f1.y;              \
            hacc[mi][ni][0] = 0u;     hacc[mi][ni][1] = 0u;                 \
        }                                                                   \
    } }

    LOADG(0);
    STORES(0);
    __syncthreads();

    #pragma unroll 1
    for (int kt = 0; kt < K_ITERS; kt++) {
        if (kt + 1 < K_ITERS) LOADG(kt + 1);
        COMPUTE(kt & 1);
        if ((kt & 3) == 3) PROMOTE();   // K-chunk = 128 -> bounded f16 walk
        if (kt + 1 < K_ITERS) {
            STORES((kt + 1) & 1);
            __syncthreads();
        }
    }
#undef LOADG
#undef STORES
#undef COMPUTE
#undef PROMOTE

    // Epilogue: energy = tanh(accf + dec_proj), partial = sum_col energy * v
    float rs[8];
    #pragma unroll
    for (int i = 0; i < 8; i++) rs[i] = 0.f;

    #pragma unroll
    for (int mi = 0; mi < 4; mi++) {
        #pragma unroll
        for (int ni = 0; ni < 4; ni++) {
            int c0 = warpN * 32 + ni * 8 + 2 * t;
            float d0 = dp_sh[c0],     d1 = dp_sh[c0 + 1];
            float w0 = v_sh[c0],      w1 = v_sh[c0 + 1];
            rs[2 * mi]     += fast_tanh(accf[mi][ni][0] + d0) * w0
                            + fast_tanh(accf[mi][ni][1] + d1) * w1;
            rs[2 * mi + 1] += fast_tanh(accf[mi][ni][2] + d0) * w0
                            + fast_tanh(accf[mi][ni][3] + d1) * w1;
        }
    }
    #pragma unroll
    for (int i = 0; i < 8; i++) {
        rs[i] += __shfl_xor_sync(0xffffffffu, rs[i], 1);
        rs[i] += __shfl_xor_sync(0xffffffffu, rs[i], 2);
    }
    if (t == 0) {
        #pragma unroll
        for (int mi = 0; mi < 4; mi++) {
            part_sh[warpN][warpM * 64 + mi * 16 + g]     = rs[2 * mi];
            part_sh[warpN][warpM * 64 + mi * 16 + g + 8] = rs[2 * mi + 1];
        }
    }
    __syncthreads();
    if (tid < 128) {
        float sres = part_sh[0][tid] + part_sh[1][tid]
                   + part_sh[2][tid] + part_sh[3][tid];
        g_part[(size_t)blockIdx.x * M_ + mBase + tid] = sres;
    }
}

// ---------------------------------------------------------------------------
__global__ void softmax_kernel(const void* __restrict__ mask,
                               float* __restrict__ attn) {
    const int b   = blockIdx.x;
    const int tid = threadIdx.x;  // 256
    __shared__ float red[8];
    const int mode = g_mask_mode;

    float vals[8];
    float lmax = -1e30f;
    #pragma unroll
    for (int i = 0; i < 8; i++) {
        size_t f = (size_t)b * S_ + tid + i * 256;
        float sc = 0.f;
        #pragma unroll
        for (int x = 0; x < NTILES; x++) sc += g_part[(size_t)x * M_ + f];
        bool alive;
        if (mode == 0)      alive = ((const unsigned char*)mask)[f] != 0;
        else if (mode == 1) alive = ((const int*)mask)[f] != 0;
        else                alive = ((const float*)mask)[f] != 0.0f;
        if (!alive) sc = -1e9f;
        vals[i] = sc;
        lmax = fmaxf(lmax, sc);
    }
    float m = lmax;
    #pragma unroll
    for (int off = 16; off; off >>= 1)
        m = fmaxf(m, __shfl_xor_sync(0xffffffffu, m, off));
    if ((tid & 31) == 0) red[tid >> 5] = m;
    __syncthreads();
    float bm = red[0];
    #pragma unroll
    for (int i = 1; i < 8; i++) bm = fmaxf(bm, red[i]);

    float lsum = 0.f;
    #pragma unroll
    for (int i = 0; i < 8; i++) {
        vals[i] = expf(vals[i] - bm);
        lsum += vals[i];
    }
    #pragma unroll
    for (int off = 16; off; off >>= 1)
        lsum += __shfl_xor_sync(0xffffffffu, lsum, off);
    __syncthreads();
    if ((tid & 31) == 0) red[tid >> 5] = lsum;
    __syncthreads();
    float tot = 0.f;
    #pragma unroll
    for (int i = 0; i < 8; i++) tot += red[i];
    float inv = 1.f / tot;

    #pragma unroll
    for (int i = 0; i < 8; i++)
        attn[(size_t)b * S_ + tid + i * 256] = vals[i] * inv;
}

// ---------------------------------------------------------------------------
__global__ void context_kernel(const float* __restrict__ enc,
                               const float* __restrict__ attn,
                               float* __restrict__ ctx) {
    const int b  = blockIdx.x;
    const int h  = blockIdx.y * 128 + (threadIdx.x & 127);
    const int sp = threadIdx.x >> 7;
    const float* e = enc  + (size_t)b * S_ * H_ + h;
    const float* w = attn + (size_t)b * S_;
    float acc = 0.f;
    #pragma unroll 8
    for (int s = sp; s < S_; s += 2)
        acc = fmaf(w[s], e[(size_t)s * H_], acc);
    __shared__ float sh[256];
    sh[threadIdx.x] = acc;
    __syncthreads();
    if (threadIdx.x < 128)
        ctx[(size_t)b * H_ + h] = sh[threadIdx.x] + sh[threadIdx.x + 128];
}

// ---------------------------------------------------------------------------
extern "C" void kernel_launch(void* const* d_in, const int* in_sizes, int n_in,
                              void* d_out, int out_size) {
    (void)in_sizes; (void)n_in; (void)out_size;
    const float* dec  = (const float*)d_in[0];
    const float* enc  = (const float*)d_in[1];
    const void*  mask = (const void*)d_in[2];
    const float* Wenc = (const float*)d_in[3];
    const float* Wdec = (const float*)d_in[4];
    const float* v    = (const float*)d_in[5];
    float* out  = (float*)d_out;
    float* attn = out + (size_t)B_ * H_;

    sniff_mask_kernel<<<1, 1>>>((const unsigned int*)mask);
    dec_proj_kernel<<<2048, 256>>>(dec, Wdec);
    dim3 g2(NTILES, M_ / 128);      // (8, 1024), x fastest -> A reuse in L2
    fused_score_kernel<<<g2, 256>>>(enc, Wenc, v);
    softmax_kernel<<<B_, 256>>>(mask, attn);
    context_kernel<<<dim3(B_, H_ / 128), 256>>>(enc, attn, out);
}

// round 8
// speedup vs baseline: 1.9967x; 1.9967x over previous
#include <cuda_runtime.h>
#include <cuda_fp16.h>
#include <cstdint>
#include <math.h>

#define B_ 64
#define S_ 2048
#define H_ 1024
#define M_ (B_*S_)
#define NTILES 8          // H_/128 N-blocks
#define KT 32             // k elems per tile
#define K_ITERS (H_/KT)   // 32
#define RS 80             // smem row stride bytes (padded, ldmatrix conflict-free)
#define ASTAGE (128*RS)   // 10240 B per operand stage
#define NSTG 4

__device__ float  g_dp[B_ * H_];
__device__ float  g_part[NTILES * M_];
__device__ int    g_mask_mode;
__device__ __half g_ench[(size_t)M_ * H_];   // 256 MB fp16 copy of enc
__device__ __half g_wh[(size_t)H_ * H_];     // 2 MB fp16 copy of W_enc

__device__ __forceinline__ uint32_t smem_u32(const void* p) {
    uint32_t a;
    asm("{ .reg .u64 t; cvta.to.shared.u64 t, %1; cvt.u32.u64 %0, t; }" : "=r"(a) : "l"(p));
    return a;
}
__device__ __forceinline__ void cp_async16(uint32_t dst, const void* src) {
    asm volatile("cp.async.cg.shared.global [%0], [%1], 16;" :: "r"(dst), "l"(src));
}
__device__ __forceinline__ void ldsm_x4(uint32_t r[4], uint32_t addr) {
    asm volatile("ldmatrix.sync.aligned.m8n8.x4.shared.b16 {%0,%1,%2,%3}, [%4];"
                 : "=r"(r[0]), "=r"(r[1]), "=r"(r[2]), "=r"(r[3]) : "r"(addr));
}
__device__ __forceinline__ void mma_f16(float c[4], const uint32_t a[4],
                                        uint32_t b0, uint32_t b1) {
    asm volatile(
        "mma.sync.aligned.m16n8k16.row.col.f32.f16.f16.f32 "
        "{%0,%1,%2,%3}, {%4,%5,%6,%7}, {%8,%9}, {%0,%1,%2,%3};"
        : "+f"(c[0]), "+f"(c[1]), "+f"(c[2]), "+f"(c[3])
        : "r"(a[0]), "r"(a[1]), "r"(a[2]), "r"(a[3]), "r"(b0), "r"(b1));
}
__device__ __forceinline__ float fast_tanh(float x) {
    float y; asm("tanh.approx.f32 %0, %1;" : "=f"(y) : "f"(x)); return y;
}

// ---------------------------------------------------------------------------
__global__ void sniff_mask_kernel(const unsigned int* __restrict__ m) {
    unsigned w = m[0];
    int mode;
    if (w == 0x01010101u)      mode = 0;  // uint8/bool
    else if (w == 0x3F800000u) mode = 2;  // float32
    else                       mode = 1;  // int32
    g_mask_mode = mode;
}

// ---------------------------------------------------------------------------
// fp32 -> fp16 conversions (one 8-elem chunk per thread)
// ---------------------------------------------------------------------------
__global__ void cvt_enc_kernel(const float* __restrict__ src) {
    size_t c = (size_t)blockIdx.x * blockDim.x + threadIdx.x;   // 16.7M threads
    const float4* s = (const float4*)src + c * 2;
    float4 a = s[0], b = s[1];
    __half2 h[4];
    h[0] = __floats2half2_rn(a.x, a.y);
    h[1] = __floats2half2_rn(a.z, a.w);
    h[2] = __floats2half2_rn(b.x, b.y);
    h[3] = __floats2half2_rn(b.z, b.w);
    *((uint4*)g_ench + c) = *(uint4*)h;
}
__global__ void cvt_w_kernel(const float* __restrict__ src) {
    size_t c = (size_t)blockIdx.x * blockDim.x + threadIdx.x;   // 131072 threads
    const float4* s = (const float4*)src + c * 2;
    float4 a = s[0], b = s[1];
    __half2 h[4];
    h[0] = __floats2half2_rn(a.x, a.y);
    h[1] = __floats2half2_rn(a.z, a.w);
    h[2] = __floats2half2_rn(b.x, b.y);
    h[3] = __floats2half2_rn(b.z, b.w);
    *((uint4*)g_wh + c) = *(uint4*)h;
}

// ---------------------------------------------------------------------------
__global__ void dec_proj_kernel(const float* __restrict__ dec,
                                const float* __restrict__ Wdec) {
    int wid  = (blockIdx.x * blockDim.x + threadIdx.x) >> 5;
    int lane = threadIdx.x & 31;
    int o  = wid >> 4;
    int b0 = (wid & 15) * 4;
    const float* wr = Wdec + (size_t)o * H_;
    const float* d0 = dec + (size_t)(b0 + 0) * H_;
    const float* d1 = dec + (size_t)(b0 + 1) * H_;
    const float* d2 = dec + (size_t)(b0 + 2) * H_;
    const float* d3 = dec + (size_t)(b0 + 3) * H_;
    float a0 = 0.f, a1 = 0.f, a2 = 0.f, a3 = 0.f;
    #pragma unroll 4
    for (int h = lane; h < H_; h += 32) {
        float w = wr[h];
        a0 = fmaf(w, d0[h], a0);
        a1 = fmaf(w, d1[h], a1);
        a2 = fmaf(w, d2[h], a2);
        a3 = fmaf(w, d3[h], a3);
    }
    #pragma unroll
    for (int off = 16; off; off >>= 1) {
        a0 += __shfl_down_sync(0xffffffffu, a0, off);
        a1 += __shfl_down_sync(0xffffffffu, a1, off);
        a2 += __shfl_down_sync(0xffffffffu, a2, off);
        a3 += __shfl_down_sync(0xffffffffu, a3, off);
    }
    if (lane == 0) {
        g_dp[(size_t)(b0 + 0) * H_ + o] = a0;
        g_dp[(size_t)(b0 + 1) * H_ + o] = a1;
        g_dp[(size_t)(b0 + 2) * H_ + o] = a2;
        g_dp[(size_t)(b0 + 3) * H_ + o] = a3;
    }
}

// ---------------------------------------------------------------------------
// Fused fp16 MMA GEMM (encH @ WencH^T) + tanh(.+dec_proj).v partial reduction.
// Operands pre-converted to fp16 in gmem; cp.async 4-stage ring; one sync/ktile.
// Block 128(M)x128(N); 8 warps 2(M)x4(N); warp tile 64x32; f32 accumulators.
// ---------------------------------------------------------------------------
__global__ void __launch_bounds__(256, 2)
fused_score_kernel(const float* __restrict__ v) {
    __shared__ __align__(16) char smA[NSTG][ASTAGE];
    __shared__ __align__(16) char smB[NSTG][ASTAGE];
    __shared__ float dp_sh[128];
    __shared__ float v_sh[128];
    __shared__ float part_sh[4][128];

    const int tid   = threadIdx.x;
    const int lane  = tid & 31;
    const int warp  = tid >> 5;
    const int warpM = warp & 1;
    const int warpN = warp >> 1;
    const int g = lane >> 2;
    const int t = lane & 3;

    const int nBase = blockIdx.x * 128;
    const int mBase = blockIdx.y * 128;
    const int b     = mBase >> 11;

    if (tid < 128) {
        dp_sh[tid] = g_dp[(size_t)b * H_ + nBase + tid];
        v_sh[tid]  = v[nBase + tid];
    }

    const uint32_t smA0 = smem_u32(&smA[0][0]);
    const uint32_t smB0 = smem_u32(&smB[0][0]);
    const __half* encH = g_ench;
    const __half* wH   = g_wh;

    float acc[4][4][4];
    #pragma unroll
    for (int mi = 0; mi < 4; mi++)
        #pragma unroll
        for (int ni = 0; ni < 4; ni++)
            #pragma unroll
            for (int c = 0; c < 4; c++) acc[mi][ni][c] = 0.f;

    // per-thread cp.async slots: 2 chunks A + 2 chunks B of 16B
    const int c0_ = 2 * tid;            // chunk ids c0_, c0_+1 (0..511)
    const int r0_ = c0_ >> 2,        q0_ = c0_ & 3;
    const int r1_ = (c0_ + 1) >> 2,  q1_ = (c0_ + 1) & 3;

#define ISSUE(J) {                                                          \
    const int s_ = (J) & (NSTG - 1);                                        \
    const uint32_t sa_ = smA0 + s_ * ASTAGE;                                \
    const uint32_t sb_ = smB0 + s_ * ASTAGE;                                \
    const size_t ko_ = (size_t)(J) * KT;                                    \
    cp_async16(sa_ + r0_ * RS + q0_ * 16,                                   \
               encH + (size_t)(mBase + r0_) * H_ + ko_ + q0_ * 8);          \
    cp_async16(sa_ + r1_ * RS + q1_ * 16,                                   \
               encH + (size_t)(mBase + r1_) * H_ + ko_ + q1_ * 8);          \
    cp_async16(sb_ + r0_ * RS + q0_ * 16,                                   \
               wH + (size_t)(nBase + r0_) * H_ + ko_ + q0_ * 8);            \
    cp_async16(sb_ + r1_ * RS + q1_ * 16,                                   \
               wH + (size_t)(nBase + r1_) * H_ + ko_ + q1_ * 8);            \
    }

    // ldmatrix per-lane address components
    const int aRow = warpM * 64 + (lane & 7) + ((lane >> 3) & 1) * 8;
    const int aCol = ((lane >> 4) & 1) * 16;
    const int bRow = warpN * 32 + (lane >> 4) * 8 + (lane & 7);
    const int bCol = ((lane >> 3) & 1) * 16;

#define COMPUTE(BUF) {                                                     \
    const uint32_t Ab = smA0 + (BUF) * ASTAGE;                              \
    const uint32_t Bb = smB0 + (BUF) * ASTAGE;                              \
    _Pragma("unroll")                                                       \
    for (int ks = 0; ks < 2; ks++) {                                        \
        uint32_t af[4][4], bf[2][4];                                        \
        _Pragma("unroll")                                                   \
        for (int mi = 0; mi < 4; mi++)                                      \
            ldsm_x4(af[mi], Ab + (aRow + mi * 16) * RS + ks * 32 + aCol);   \
        _Pragma("unroll")                                                   \
        for (int nj = 0; nj < 2; nj++)                                      \
            ldsm_x4(bf[nj], Bb + (bRow + nj * 16) * RS + ks * 32 + bCol);   \
        _Pragma("unroll")                                                   \
        for (int mi = 0; mi < 4; mi++) {                                    \
            _Pragma("unroll")                                               \
            for (int nj = 0; nj < 2; nj++) {                                \
                mma_f16(acc[mi][2*nj],   af[mi], bf[nj][0], bf[nj][1]);     \
                mma_f16(acc[mi][2*nj+1], af[mi], bf[nj][2], bf[nj][3]);     \
            }                                                               \
        }                                                                   \
    } }

    // prologue: 3 stages in flight
    ISSUE(0); asm volatile("cp.async.commit_group;");
    ISSUE(1); asm volatile("cp.async.commit_group;");
    ISSUE(2); asm volatile("cp.async.commit_group;");

    #pragma unroll 1
    for (int kt = 0; kt < K_ITERS; kt++) {
        asm volatile("cp.async.wait_group 2;");
        __syncthreads();
        COMPUTE(kt & (NSTG - 1));
        if (kt + 3 < K_ITERS) ISSUE(kt + 3);
        asm volatile("cp.async.commit_group;");
    }
#undef ISSUE
#undef COMPUTE

    // Epilogue: energy = tanh(acc + dec_proj), partial = sum_col energy * v
    float rs[8];
    #pragma unroll
    for (int i = 0; i < 8; i++) rs[i] = 0.f;

    #pragma unroll
    for (int mi = 0; mi < 4; mi++) {
        #pragma unroll
        for (int ni = 0; ni < 4; ni++) {
            int c0 = warpN * 32 + ni * 8 + 2 * t;
            float d0 = dp_sh[c0],     d1 = dp_sh[c0 + 1];
            float w0 = v_sh[c0],      w1 = v_sh[c0 + 1];
            rs[2 * mi]     += fast_tanh(acc[mi][ni][0] + d0) * w0
                            + fast_tanh(acc[mi][ni][1] + d1) * w1;
            rs[2 * mi + 1] += fast_tanh(acc[mi][ni][2] + d0) * w0
                            + fast_tanh(acc[mi][ni][3] + d1) * w1;
        }
    }
    #pragma unroll
    for (int i = 0; i < 8; i++) {
        rs[i] += __shfl_xor_sync(0xffffffffu, rs[i], 1);
        rs[i] += __shfl_xor_sync(0xffffffffu, rs[i], 2);
    }
    if (t == 0) {
        #pragma unroll
        for (int mi = 0; mi < 4; mi++) {
            part_sh[warpN][warpM * 64 + mi * 16 + g]     = rs[2 * mi];
            part_sh[warpN][warpM * 64 + mi * 16 + g + 8] = rs[2 * mi + 1];
        }
    }
    __syncthreads();
    if (tid < 128) {
        float sres = part_sh[0][tid] + part_sh[1][tid]
                   + part_sh[2][tid] + part_sh[3][tid];
        g_part[(size_t)blockIdx.x * M_ + mBase + tid] = sres;
    }
}

// ---------------------------------------------------------------------------
__global__ void softmax_kernel(const void* __restrict__ mask,
                               float* __restrict__ attn) {
    const int b   = blockIdx.x;
    const int tid = threadIdx.x;  // 256
    __shared__ float red[8];
    const int mode = g_mask_mode;

    float vals[8];
    float lmax = -1e30f;
    #pragma unroll
    for (int i = 0; i < 8; i++) {
        size_t f = (size_t)b * S_ + tid + i * 256;
        float sc = 0.f;
        #pragma unroll
        for (int x = 0; x < NTILES; x++) sc += g_part[(size_t)x * M_ + f];
        bool alive;
        if (mode == 0)      alive = ((const unsigned char*)mask)[f] != 0;
        else if (mode == 1) alive = ((const int*)mask)[f] != 0;
        else                alive = ((const float*)mask)[f] != 0.0f;
        if (!alive) sc = -1e9f;
        vals[i] = sc;
        lmax = fmaxf(lmax, sc);
    }
    float m = lmax;
    #pragma unroll
    for (int off = 16; off; off >>= 1)
        m = fmaxf(m, __shfl_xor_sync(0xffffffffu, m, off));
    if ((tid & 31) == 0) red[tid >> 5] = m;
    __syncthreads();
    float bm = red[0];
    #pragma unroll
    for (int i = 1; i < 8; i++) bm = fmaxf(bm, red[i]);

    float lsum = 0.f;
    #pragma unroll
    for (int i = 0; i < 8; i++) {
        vals[i] = expf(vals[i] - bm);
        lsum += vals[i];
    }
    #pragma unroll
    for (int off = 16; off; off >>= 1)
        lsum += __shfl_xor_sync(0xffffffffu, lsum, off);
    __syncthreads();
    if ((tid & 31) == 0) red[tid >> 5] = lsum;
    __syncthreads();
    float tot = 0.f;
    #pragma unroll
    for (int i = 0; i < 8; i++) tot += red[i];
    float inv = 1.f / tot;

    #pragma unroll
    for (int i = 0; i < 8; i++)
        attn[(size_t)b * S_ + tid + i * 256] = vals[i] * inv;
}

// ---------------------------------------------------------------------------
__global__ void context_kernel(const float* __restrict__ enc,
                               const float* __restrict__ attn,
                               float* __restrict__ ctx) {
    const int b  = blockIdx.x;
    const int h  = blockIdx.y * 128 + (threadIdx.x & 127);
    const int sp = threadIdx.x >> 7;
    const float* e = enc  + (size_t)b * S_ * H_ + h;
    const float* w = attn + (size_t)b * S_;
    float acc = 0.f;
    #pragma unroll 8
    for (int s = sp; s < S_; s += 2)
        acc = fmaf(w[s], e[(size_t)s * H_], acc);
    __shared__ float sh[256];
    sh[threadIdx.x] = acc;
    __syncthreads();
    if (threadIdx.x < 128)
        ctx[(size_t)b * H_ + h] = sh[threadIdx.x] + sh[threadIdx.x + 128];
}

// ---------------------------------------------------------------------------
extern "C" void kernel_launch(void* const* d_in, const int* in_sizes, int n_in,
                              void* d_out, int out_size) {
    (void)in_sizes; (void)n_in; (void)out_size;
    const float* dec  = (const float*)d_in[0];
    const float* enc  = (const float*)d_in[1];
    const void*  mask = (const void*)d_in[2];
    const float* Wenc = (const float*)d_in[3];
    const float* Wdec = (const float*)d_in[4];
    const float* v    = (const float*)d_in[5];
    float* out  = (float*)d_out;
    float* attn = out + (size_t)B_ * H_;

    sniff_mask_kernel<<<1, 1>>>((const unsigned int*)mask);
    cvt_enc_kernel<<<65536, 256>>>(enc);     // 128M elems / 8 per thread
    cvt_w_kernel<<<512, 256>>>(Wenc);        // 1M elems / 8 per thread
    dec_proj_kernel<<<2048, 256>>>(dec, Wdec);
    dim3 g2(NTILES, M_ / 128);               // (8, 1024), x fastest -> L2 reuse
    fused_score_kernel<<<g2, 256>>>(v);
    softmax_kernel<<<B_, 256>>>(mask, attn);
    context_kernel<<<dim3(B_, H_ / 128), 256>>>(enc, attn, out);
}

// round 9
// speedup vs baseline: 2.0732x; 1.0383x over previous
#include <cuda_runtime.h>
#include <cuda_fp16.h>
#include <cstdint>
#include <math.h>

#define B_ 64
#define S_ 2048
#define H_ 1024
#define M_ (B_*S_)
#define NTILES 8          // H_/128 N-blocks
#define KT 32             // k elems per tile
#define K_ITERS (H_/KT)   // 32
#define RS 80             // smem row stride bytes (padded, ldmatrix conflict-free)
#define MT 256            // CTA tile M
#define NT 128            // CTA tile N
#define ASTG (MT*RS)      // 20480
#define BSTG (NT*RS)      // 10240
#define STG  (ASTG+BSTG)  // 30720
#define NSTG 4
#define DYN_BYTES (NSTG*STG)   // 122880

__device__ float  g_dp[B_ * H_];
__device__ float  g_part[NTILES * M_];
__device__ int    g_mask_mode;
__device__ __half g_ench[(size_t)M_ * H_];   // 256 MB fp16 copy of enc
__device__ __half g_wh[(size_t)H_ * H_];     // 2 MB fp16 copy of W_enc

__device__ __forceinline__ uint32_t smem_u32(const void* p) {
    uint32_t a;
    asm("{ .reg .u64 t; cvta.to.shared.u64 t, %1; cvt.u32.u64 %0, t; }" : "=r"(a) : "l"(p));
    return a;
}
__device__ __forceinline__ void cp_async16(uint32_t dst, const void* src) {
    asm volatile("cp.async.cg.shared.global [%0], [%1], 16;" :: "r"(dst), "l"(src));
}
__device__ __forceinline__ void ldsm_x4(uint32_t r[4], uint32_t addr) {
    asm volatile("ldmatrix.sync.aligned.m8n8.x4.shared.b16 {%0,%1,%2,%3}, [%4];"
                 : "=r"(r[0]), "=r"(r[1]), "=r"(r[2]), "=r"(r[3]) : "r"(addr));
}
__device__ __forceinline__ void mma_f16(float c[4], const uint32_t a[4],
                                        uint32_t b0, uint32_t b1) {
    asm volatile(
        "mma.sync.aligned.m16n8k16.row.col.f32.f16.f16.f32 "
        "{%0,%1,%2,%3}, {%4,%5,%6,%7}, {%8,%9}, {%0,%1,%2,%3};"
        : "+f"(c[0]), "+f"(c[1]), "+f"(c[2]), "+f"(c[3])
        : "r"(a[0]), "r"(a[1]), "r"(a[2]), "r"(a[3]), "r"(b0), "r"(b1));
}
__device__ __forceinline__ float fast_tanh(float x) {
    float y; asm("tanh.approx.f32 %0, %1;" : "=f"(y) : "f"(x)); return y;
}

// ---------------------------------------------------------------------------
__global__ void sniff_mask_kernel(const unsigned int* __restrict__ m) {
    unsigned w = m[0];
    int mode;
    if (w == 0x01010101u)      mode = 0;  // uint8/bool
    else if (w == 0x3F800000u) mode = 2;  // float32
    else                       mode = 1;  // int32
    g_mask_mode = mode;
}

// ---------------------------------------------------------------------------
__global__ void cvt_enc_kernel(const float* __restrict__ src) {
    size_t c = (size_t)blockIdx.x * blockDim.x + threadIdx.x;
    const float4* s = (const float4*)src + c * 2;
    float4 a = s[0], b = s[1];
    __half2 h[4];
    h[0] = __floats2half2_rn(a.x, a.y);
    h[1] = __floats2half2_rn(a.z, a.w);
    h[2] = __floats2half2_rn(b.x, b.y);
    h[3] = __floats2half2_rn(b.z, b.w);
    *((uint4*)g_ench + c) = *(uint4*)h;
}
__global__ void cvt_w_kernel(const float* __restrict__ src) {
    size_t c = (size_t)blockIdx.x * blockDim.x + threadIdx.x;
    const float4* s = (const float4*)src + c * 2;
    float4 a = s[0], b = s[1];
    __half2 h[4];
    h[0] = __floats2half2_rn(a.x, a.y);
    h[1] = __floats2half2_rn(a.z, a.w);
    h[2] = __floats2half2_rn(b.x, b.y);
    h[3] = __floats2half2_rn(b.z, b.w);
    *((uint4*)g_wh + c) = *(uint4*)h;
}

// ---------------------------------------------------------------------------
__global__ void dec_proj_kernel(const float* __restrict__ dec,
                                const float* __restrict__ Wdec) {
    int wid  = (blockIdx.x * blockDim.x + threadIdx.x) >> 5;
    int lane = threadIdx.x & 31;
    int o  = wid >> 4;
    int b0 = (wid & 15) * 4;
    const float* wr = Wdec + (size_t)o * H_;
    const float* d0 = dec + (size_t)(b0 + 0) * H_;
    const float* d1 = dec + (size_t)(b0 + 1) * H_;
    const float* d2 = dec + (size_t)(b0 + 2) * H_;
    const float* d3 = dec + (size_t)(b0 + 3) * H_;
    float a0 = 0.f, a1 = 0.f, a2 = 0.f, a3 = 0.f;
    #pragma unroll 4
    for (int h = lane; h < H_; h += 32) {
        float w = wr[h];
        a0 = fmaf(w, d0[h], a0);
        a1 = fmaf(w, d1[h], a1);
        a2 = fmaf(w, d2[h], a2);
        a3 = fmaf(w, d3[h], a3);
    }
    #pragma unroll
    for (int off = 16; off; off >>= 1) {
        a0 += __shfl_down_sync(0xffffffffu, a0, off);
        a1 += __shfl_down_sync(0xffffffffu, a1, off);
        a2 += __shfl_down_sync(0xffffffffu, a2, off);
        a3 += __shfl_down_sync(0xffffffffu, a3, off);
    }
    if (lane == 0) {
        g_dp[(size_t)(b0 + 0) * H_ + o] = a0;
        g_dp[(size_t)(b0 + 1) * H_ + o] = a1;
        g_dp[(size_t)(b0 + 2) * H_ + o] = a2;
        g_dp[(size_t)(b0 + 3) * H_ + o] = a3;
    }
}

// ---------------------------------------------------------------------------
// Fused fp16 MMA GEMM (encH @ WencH^T) + tanh(.+dec_proj).v partial reduction.
// CTA tile 256(M)x128(N); 8 warps = 4(M)x2(N), warp tile 64x64 (cuts smem
// fragment re-reads); cp.async 4-stage ring in dynamic smem; f32 accumulators.
// ---------------------------------------------------------------------------
__global__ void __launch_bounds__(256, 1)
fused_score_kernel(const float* __restrict__ v) {
    extern __shared__ __align__(16) char dynsm[];
    __shared__ float dp_sh[NT];
    __shared__ float v_sh[NT];
    __shared__ float part_sh[2][MT];

    const int tid   = threadIdx.x;
    const int lane  = tid & 31;
    const int warp  = tid >> 5;
    const int warpM = warp & 3;     // 0..3
    const int warpN = warp >> 2;    // 0..1
    const int g = lane >> 2;
    const int t = lane & 3;

    const int nBase = blockIdx.x * NT;
    const int mBase = blockIdx.y * MT;
    const int b     = mBase >> 11;  // 256 | 2048 -> single batch per tile

    if (tid < NT) {
        dp_sh[tid] = g_dp[(size_t)b * H_ + nBase + tid];
        v_sh[tid]  = v[nBase + tid];
    }

    const uint32_t sm0 = smem_u32(dynsm);
    const __half* encH = g_ench;
    const __half* wH   = g_wh;

    float acc[4][8][4];
    #pragma unroll
    for (int mi = 0; mi < 4; mi++)
        #pragma unroll
        for (int ni = 0; ni < 8; ni++)
            #pragma unroll
            for (int c = 0; c < 4; c++) acc[mi][ni][c] = 0.f;

    // cp.async: per ktile A = 1024 chunks (16B), B = 512 chunks; 256 threads.
#define ISSUE(J) {                                                          \
    const uint32_t sa_ = sm0 + ((J) & (NSTG - 1)) * STG;                    \
    const uint32_t sb_ = sa_ + ASTG;                                        \
    const size_t ko_ = (size_t)(J) * KT;                                    \
    _Pragma("unroll")                                                       \
    for (int i_ = 0; i_ < 4; i_++) {                                        \
        int c_ = tid + (i_ << 8);                                           \
        int r_ = c_ >> 2, q_ = c_ & 3;                                      \
        cp_async16(sa_ + r_ * RS + q_ * 16,                                 \
                   encH + (size_t)(mBase + r_) * H_ + ko_ + q_ * 8);        \
    }                                                                       \
    _Pragma("unroll")                                                       \
    for (int i_ = 0; i_ < 2; i_++) {                                        \
        int c_ = tid + (i_ << 8);                                           \
        int r_ = c_ >> 2, q_ = c_ & 3;                                      \
        cp_async16(sb_ + r_ * RS + q_ * 16,                                 \
                   wH + (size_t)(nBase + r_) * H_ + ko_ + q_ * 8);          \
    } }

    // ldmatrix per-lane address components
    const int aRow = warpM * 64 + (lane & 7) + ((lane >> 3) & 1) * 8;
    const int aCol = ((lane >> 4) & 1) * 16;
    const int bRow = warpN * 64 + (lane >> 4) * 8 + (lane & 7);
    const int bCol = ((lane >> 3) & 1) * 16;

#define COMPUTE(BUF) {                                                     \
    const uint32_t Ab = sm0 + (BUF) * STG;                                  \
    const uint32_t Bb = Ab + ASTG;                                          \
    _Pragma("unroll")                                                       \
    for (int ks = 0; ks < 2; ks++) {                                        \
        uint32_t af[4][4], bf[4][4];                                        \
        _Pragma("unroll")                                                   \
        for (int mi = 0; mi < 4; mi++)                                      \
            ldsm_x4(af[mi], Ab + (aRow + mi * 16) * RS + ks * 32 + aCol);   \
        _Pragma("unroll")                                                   \
        for (int nj = 0; nj < 4; nj++)                                      \
            ldsm_x4(bf[nj], Bb + (bRow + nj * 16) * RS + ks * 32 + bCol);   \
        _Pragma("unroll")                                                   \
        for (int mi = 0; mi < 4; mi++) {                                    \
            _Pragma("unroll")                                               \
            for (int nj = 0; nj < 4; nj++) {                                \
                mma_f16(acc[mi][2*nj],   af[mi], bf[nj][0], bf[nj][1]);     \
                mma_f16(acc[mi][2*nj+1], af[mi], bf[nj][2], bf[nj][3]);     \
            }                                                               \
        }                                                                   \
    } }

    // prologue: 3 stages in flight
    ISSUE(0); asm volatile("cp.async.commit_group;");
    ISSUE(1); asm volatile("cp.async.commit_group;");
    ISSUE(2); asm volatile("cp.async.commit_group;");

    #pragma unroll 1
    for (int kt = 0; kt < K_ITERS; kt++) {
        asm volatile("cp.async.wait_group 2;");
        __syncthreads();
        COMPUTE(kt & (NSTG - 1));
        if (kt + 3 < K_ITERS) ISSUE(kt + 3);
        asm volatile("cp.async.commit_group;");
    }
#undef ISSUE
#undef COMPUTE

    // Epilogue: energy = tanh(acc + dec_proj), partial = sum_col energy * v
    float rs[8];
    #pragma unroll
    for (int i = 0; i < 8; i++) rs[i] = 0.f;

    #pragma unroll
    for (int mi = 0; mi < 4; mi++) {
        #pragma unroll
        for (int ni = 0; ni < 8; ni++) {
            int c0 = warpN * 64 + ni * 8 + 2 * t;
            float d0 = dp_sh[c0],     d1 = dp_sh[c0 + 1];
            float w0 = v_sh[c0],      w1 = v_sh[c0 + 1];
            rs[2 * mi]     += fast_tanh(acc[mi][ni][0] + d0) * w0
                            + fast_tanh(acc[mi][ni][1] + d1) * w1;
            rs[2 * mi + 1] += fast_tanh(acc[mi][ni][2] + d0) * w0
                            + fast_tanh(acc[mi][ni][3] + d1) * w1;
        }
    }
    #pragma unroll
    for (int i = 0; i < 8; i++) {
        rs[i] += __shfl_xor_sync(0xffffffffu, rs[i], 1);
        rs[i] += __shfl_xor_sync(0xffffffffu, rs[i], 2);
    }
    if (t == 0) {
        #pragma unroll
        for (int mi = 0; mi < 4; mi++) {
            part_sh[warpN][warpM * 64 + mi * 16 + g]     = rs[2 * mi];
            part_sh[warpN][warpM * 64 + mi * 16 + g + 8] = rs[2 * mi + 1];
        }
    }
    __syncthreads();
    // all 256 threads: one row each
    {
        float sres = part_sh[0][tid] + part_sh[1][tid];
        g_part[(size_t)blockIdx.x * M_ + mBase + tid] = sres;
    }
}

// ---------------------------------------------------------------------------
__global__ void softmax_kernel(const void* __restrict__ mask,
                               float* __restrict__ attn) {
    const int b   = blockIdx.x;
    const int tid = threadIdx.x;  // 256
    __shared__ float red[8];
    const int mode = g_mask_mode;

    float vals[8];
    float lmax = -1e30f;
    #pragma unroll
    for (int i = 0; i < 8; i++) {
        size_t f = (size_t)b * S_ + tid + i * 256;
        float sc = 0.f;
        #pragma unroll
        for (int x = 0; x < NTILES; x++) sc += g_part[(size_t)x * M_ + f];
        bool alive;
        if (mode == 0)      alive = ((const unsigned char*)mask)[f] != 0;
        else if (mode == 1) alive = ((const int*)mask)[f] != 0;
        else                alive = ((const float*)mask)[f] != 0.0f;
        if (!alive) sc = -1e9f;
        vals[i] = sc;
        lmax = fmaxf(lmax, sc);
    }
    float m = lmax;
    #pragma unroll
    for (int off = 16; off; off >>= 1)
        m = fmaxf(m, __shfl_xor_sync(0xffffffffu, m, off));
    if ((tid & 31) == 0) red[tid >> 5] = m;
    __syncthreads();
    float bm = red[0];
    #pragma unroll
    for (int i = 1; i < 8; i++) bm = fmaxf(bm, red[i]);

    float lsum = 0.f;
    #pragma unroll
    for (int i = 0; i < 8; i++) {
        vals[i] = expf(vals[i] - bm);
        lsum += vals[i];
    }
    #pragma unroll
    for (int off = 16; off; off >>= 1)
        lsum += __shfl_xor_sync(0xffffffffu, lsum, off);
    __syncthreads();
    if ((tid & 31) == 0) red[tid >> 5] = lsum;
    __syncthreads();
    float tot = 0.f;
    #pragma unroll
    for (int i = 0; i < 8; i++) tot += red[i];
    float inv = 1.f / tot;

    #pragma unroll
    for (int i = 0; i < 8; i++)
        attn[(size_t)b * S_ + tid + i * 256] = vals[i] * inv;
}

// ---------------------------------------------------------------------------
// context from fp16 enc copy: halves the read traffic (256 MB vs 512 MB).
// ---------------------------------------------------------------------------
__global__ void context_kernel(const float* __restrict__ attn,
                               float* __restrict__ ctx) {
    const int b  = blockIdx.x;
    const int h  = blockIdx.y * 128 + (threadIdx.x & 127);
    const int sp = threadIdx.x >> 7;
    const __half* e = g_ench + (size_t)b * S_ * H_ + h;
    const float* w = attn + (size_t)b * S_;
    float acc = 0.f;
    #pragma unroll 8
    for (int s = sp; s < S_; s += 2)
        acc = fmaf(w[s], __half2float(e[(size_t)s * H_]), acc);
    __shared__ float sh[256];
    sh[threadIdx.x] = acc;
    __syncthreads();
    if (threadIdx.x < 128)
        ctx[(size_t)b * H_ + h] = sh[threadIdx.x] + sh[threadIdx.x + 128];
}

// ---------------------------------------------------------------------------
extern "C" void kernel_launch(void* const* d_in, const int* in_sizes, int n_in,
                              void* d_out, int out_size) {
    (void)in_sizes; (void)n_in; (void)out_size;
    const float* dec  = (const float*)d_in[0];
    const float* enc  = (const float*)d_in[1];
    const void*  mask = (const void*)d_in[2];
    const float* Wenc = (const float*)d_in[3];
    const float* Wdec = (const float*)d_in[4];
    const float* v    = (const float*)d_in[5];
    float* out  = (float*)d_out;
    float* attn = out + (size_t)B_ * H_;

    cudaFuncSetAttribute(fused_score_kernel,
                         cudaFuncAttributeMaxDynamicSharedMemorySize, DYN_BYTES);

    // 5 launches before the fused kernel so ncu (-s 5 -c 1) profiles it.
    cvt_enc_kernel<<<65536, 256>>>(enc);                 // 1
    cvt_w_kernel<<<512, 256>>>(Wenc);                    // 2
    dec_proj_kernel<<<2048, 256>>>(dec, Wdec);           // 3
    sniff_mask_kernel<<<1, 1>>>((const unsigned int*)mask);  // 4
    sniff_mask_kernel<<<1, 1>>>((const unsigned int*)mask);  // 5 (idempotent)
    dim3 g2(NTILES, M_ / MT);                            // (8, 512)
    fused_score_kernel<<<g2, 256, DYN_BYTES>>>(v);       // 6 <- profiled
    softmax_kernel<<<B_, 256>>>(mask, attn);
    context_kernel<<<dim3(B_, H_ / 128), 256>>>(attn, out);
}

// round 10
// speedup vs baseline: 2.2538x; 1.0871x over previous
#include <cuda_runtime.h>
#include <cuda_fp16.h>
#include <cstdint>
#include <math.h>

#define B_ 64
#define S_ 2048
#define H_ 1024
#define M_ (B_*S_)
#define NTILES 8          // H_/128 N-blocks
#define KT 64             // k elems per tile
#define K_ITERS (H_/KT)   // 16
#define RS 144            // smem row stride bytes (128B data + 16 pad)
#define MT 256            // CTA tile M
#define NT 128            // CTA tile N
#define ASTG (MT*RS)      // 36864
#define BSTG (NT*RS)      // 18432
#define STG  (ASTG+BSTG)  // 55296
#define NSTG 3
#define DYN_BYTES (NSTG*STG)   // 165888

__device__ float  g_dp[B_ * H_];
__device__ float  g_part[NTILES * M_];
__device__ __half g_ench[(size_t)M_ * H_];   // 256 MB fp16 copy of enc
__device__ __half g_wh[(size_t)H_ * H_];     // 2 MB fp16 copy of W_enc

__device__ __forceinline__ uint32_t smem_u32(const void* p) {
    uint32_t a;
    asm("{ .reg .u64 t; cvta.to.shared.u64 t, %1; cvt.u32.u64 %0, t; }" : "=r"(a) : "l"(p));
    return a;
}
__device__ __forceinline__ void cp_async16(uint32_t dst, const void* src) {
    asm volatile("cp.async.cg.shared.global [%0], [%1], 16;" :: "r"(dst), "l"(src));
}
__device__ __forceinline__ void ldsm_x4(uint32_t r[4], uint32_t addr) {
    asm volatile("ldmatrix.sync.aligned.m8n8.x4.shared.b16 {%0,%1,%2,%3}, [%4];"
                 : "=r"(r[0]), "=r"(r[1]), "=r"(r[2]), "=r"(r[3]) : "r"(addr));
}
__device__ __forceinline__ void mma_f16(float c[4], const uint32_t a[4],
                                        uint32_t b0, uint32_t b1) {
    asm volatile(
        "mma.sync.aligned.m16n8k16.row.col.f32.f16.f16.f32 "
        "{%0,%1,%2,%3}, {%4,%5,%6,%7}, {%8,%9}, {%0,%1,%2,%3};"
        : "+f"(c[0]), "+f"(c[1]), "+f"(c[2]), "+f"(c[3])
        : "r"(a[0]), "r"(a[1]), "r"(a[2]), "r"(a[3]), "r"(b0), "r"(b1));
}
__device__ __forceinline__ float fast_tanh(float x) {
    float y; asm("tanh.approx.f32 %0, %1;" : "=f"(y) : "f"(x)); return y;
}

// ---------------------------------------------------------------------------
__global__ void cvt_enc_kernel(const float* __restrict__ src) {
    size_t c = (size_t)blockIdx.x * blockDim.x + threadIdx.x;
    const float4* s = (const float4*)src + c * 2;
    float4 a = s[0], b = s[1];
    __half2 h[4];
    h[0] = __floats2half2_rn(a.x, a.y);
    h[1] = __floats2half2_rn(a.z, a.w);
    h[2] = __floats2half2_rn(b.x, b.y);
    h[3] = __floats2half2_rn(b.z, b.w);
    *((uint4*)g_ench + c) = *(uint4*)h;
}
__global__ void cvt_w_kernel(const float* __restrict__ src) {
    size_t c = (size_t)blockIdx.x * blockDim.x + threadIdx.x;
    const float4* s = (const float4*)src + c * 2;
    float4 a = s[0], b = s[1];
    __half2 h[4];
    h[0] = __floats2half2_rn(a.x, a.y);
    h[1] = __floats2half2_rn(a.z, a.w);
    h[2] = __floats2half2_rn(b.x, b.y);
    h[3] = __floats2half2_rn(b.z, b.w);
    *((uint4*)g_wh + c) = *(uint4*)h;
}

// ---------------------------------------------------------------------------
__global__ void dec_proj_kernel(const float* __restrict__ dec,
                                const float* __restrict__ Wdec) {
    int wid  = (blockIdx.x * blockDim.x + threadIdx.x) >> 5;
    int lane = threadIdx.x & 31;
    int o  = wid >> 4;
    int b0 = (wid & 15) * 4;
    const float* wr = Wdec + (size_t)o * H_;
    const float* d0 = dec + (size_t)(b0 + 0) * H_;
    const float* d1 = dec + (size_t)(b0 + 1) * H_;
    const float* d2 = dec + (size_t)(b0 + 2) * H_;
    const float* d3 = dec + (size_t)(b0 + 3) * H_;
    float a0 = 0.f, a1 = 0.f, a2 = 0.f, a3 = 0.f;
    #pragma unroll 4
    for (int h = lane; h < H_; h += 32) {
        float w = wr[h];
        a0 = fmaf(w, d0[h], a0);
        a1 = fmaf(w, d1[h], a1);
        a2 = fmaf(w, d2[h], a2);
        a3 = fmaf(w, d3[h], a3);
    }
    #pragma unroll
    for (int off = 16; off; off >>= 1) {
        a0 += __shfl_down_sync(0xffffffffu, a0, off);
        a1 += __shfl_down_sync(0xffffffffu, a1, off);
        a2 += __shfl_down_sync(0xffffffffu, a2, off);
        a3 += __shfl_down_sync(0xffffffffu, a3, off);
    }
    if (lane == 0) {
        g_dp[(size_t)(b0 + 0) * H_ + o] = a0;
        g_dp[(size_t)(b0 + 1) * H_ + o] = a1;
        g_dp[(size_t)(b0 + 2) * H_ + o] = a2;
        g_dp[(size_t)(b0 + 3) * H_ + o] = a3;
    }
}

// ---------------------------------------------------------------------------
// Fused fp16 MMA GEMM (encH @ WencH^T) + tanh(.+dec_proj).v partial reduction.
// CTA tile 256(M)x128(N), k-tile 64; 8 warps = 4(M)x2(N), warp tile 64x64;
// cp.async 3-stage ring (166 KB dynamic smem); f32 accumulators.
// ---------------------------------------------------------------------------
__global__ void __launch_bounds__(256, 1)
fused_score_kernel(const float* __restrict__ v) {
    extern __shared__ __align__(16) char dynsm[];
    __shared__ float dp_sh[NT];
    __shared__ float v_sh[NT];
    __shared__ float part_sh[2][MT];

    const int tid   = threadIdx.x;
    const int lane  = tid & 31;
    const int warp  = tid >> 5;
    const int warpM = warp & 3;     // 0..3
    const int warpN = warp >> 2;    // 0..1
    const int g = lane >> 2;
    const int t = lane & 3;

    const int nBase = blockIdx.x * NT;
    const int mBase = blockIdx.y * MT;
    const int b     = mBase >> 11;  // 256 | 2048 -> single batch per tile

    if (tid < NT) {
        dp_sh[tid] = g_dp[(size_t)b * H_ + nBase + tid];
        v_sh[tid]  = v[nBase + tid];
    }

    const uint32_t sm0 = smem_u32(dynsm);
    const __half* encH = g_ench;
    const __half* wH   = g_wh;

    float acc[4][8][4];
    #pragma unroll
    for (int mi = 0; mi < 4; mi++)
        #pragma unroll
        for (int ni = 0; ni < 8; ni++)
            #pragma unroll
            for (int c = 0; c < 4; c++) acc[mi][ni][c] = 0.f;

    // cp.async per ktile(64): A = 2048 chunks (16B), B = 1024; 256 threads.
#define ISSUE(J) {                                                          \
    const uint32_t sa_ = sm0 + ((J) % NSTG) * STG;                          \
    const uint32_t sb_ = sa_ + ASTG;                                        \
    const size_t ko_ = (size_t)(J) * KT;                                    \
    _Pragma("unroll")                                                       \
    for (int i_ = 0; i_ < 8; i_++) {                                        \
        int c_ = tid + (i_ << 8);                                           \
        int r_ = c_ >> 3, q_ = c_ & 7;                                      \
        cp_async16(sa_ + r_ * RS + q_ * 16,                                 \
                   encH + (size_t)(mBase + r_) * H_ + ko_ + q_ * 8);        \
    }                                                                       \
    _Pragma("unroll")                                                       \
    for (int i_ = 0; i_ < 4; i_++) {                                        \
        int c_ = tid + (i_ << 8);                                           \
        int r_ = c_ >> 3, q_ = c_ & 7;                                      \
        cp_async16(sb_ + r_ * RS + q_ * 16,                                 \
                   wH + (size_t)(nBase + r_) * H_ + ko_ + q_ * 8);          \
    } }

    // ldmatrix per-lane address components
    const int aRow = warpM * 64 + (lane & 7) + ((lane >> 3) & 1) * 8;
    const int aCol = ((lane >> 4) & 1) * 16;
    const int bRow = warpN * 64 + (lane >> 4) * 8 + (lane & 7);
    const int bCol = ((lane >> 3) & 1) * 16;

#define COMPUTE(BUF) {                                                     \
    const uint32_t Ab = sm0 + (BUF) * STG;                                  \
    const uint32_t Bb = Ab + ASTG;                                          \
    _Pragma("unroll")                                                       \
    for (int ks = 0; ks < 4; ks++) {                                        \
        uint32_t af[4][4], bf[4][4];                                        \
        _Pragma("unroll")                                                   \
        for (int mi = 0; mi < 4; mi++)                                      \
            ldsm_x4(af[mi], Ab + (aRow + mi * 16) * RS + ks * 32 + aCol);   \
        _Pragma("unroll")                                                   \
        for (int nj = 0; nj < 4; nj++)                                      \
            ldsm_x4(bf[nj], Bb + (bRow + nj * 16) * RS + ks * 32 + bCol);   \
        _Pragma("unroll")                                                   \
        for (int mi = 0; mi < 4; mi++) {                                    \
            _Pragma("unroll")                                               \
            for (int nj = 0; nj < 4; nj++) {                                \
                mma_f16(acc[mi][2*nj],   af[mi], bf[nj][0], bf[nj][1]);     \
                mma_f16(acc[mi][2*nj+1], af[mi], bf[nj][2], bf[nj][3]);     \
            }                                                               \
        }                                                                   \
    } }

    // prologue: 2 stages in flight
    ISSUE(0); asm volatile("cp.async.commit_group;");
    ISSUE(1); asm volatile("cp.async.commit_group;");

    #pragma unroll 1
    for (int kt = 0; kt < K_ITERS; kt++) {
        asm volatile("cp.async.wait_group 1;");
        __syncthreads();
        COMPUTE(kt % NSTG);
        if (kt + 2 < K_ITERS) ISSUE(kt + 2);
        asm volatile("cp.async.commit_group;");
    }
#undef ISSUE
#undef COMPUTE

    // Epilogue: energy = tanh(acc + dec_proj), partial = sum_col energy * v
    float rs[8];
    #pragma unroll
    for (int i = 0; i < 8; i++) rs[i] = 0.f;

    #pragma unroll
    for (int mi = 0; mi < 4; mi++) {
        #pragma unroll
        for (int ni = 0; ni < 8; ni++) {
            int c0 = warpN * 64 + ni * 8 + 2 * t;
            float d0 = dp_sh[c0],     d1 = dp_sh[c0 + 1];
            float w0 = v_sh[c0],      w1 = v_sh[c0 + 1];
            rs[2 * mi]     += fast_tanh(acc[mi][ni][0] + d0) * w0
                            + fast_tanh(acc[mi][ni][1] + d1) * w1;
            rs[2 * mi + 1] += fast_tanh(acc[mi][ni][2] + d0) * w0
                            + fast_tanh(acc[mi][ni][3] + d1) * w1;
        }
    }
    #pragma unroll
    for (int i = 0; i < 8; i++) {
        rs[i] += __shfl_xor_sync(0xffffffffu, rs[i], 1);
        rs[i] += __shfl_xor_sync(0xffffffffu, rs[i], 2);
    }
    if (t == 0) {
        #pragma unroll
        for (int mi = 0; mi < 4; mi++) {
            part_sh[warpN][warpM * 64 + mi * 16 + g]     = rs[2 * mi];
            part_sh[warpN][warpM * 64 + mi * 16 + g + 8] = rs[2 * mi + 1];
        }
    }
    __syncthreads();
    {
        float sres = part_sh[0][tid] + part_sh[1][tid];
        g_part[(size_t)blockIdx.x * M_ + mBase + tid] = sres;
    }
}

// ---------------------------------------------------------------------------
// Softmax; mask dtype sniffed inline from word 0 (uint8 / int32 / float32).
// ---------------------------------------------------------------------------
__global__ void softmax_kernel(const void* __restrict__ mask,
                               float* __restrict__ attn) {
    const int b   = blockIdx.x;
    const int tid = threadIdx.x;  // 256
    __shared__ float red[8];

    unsigned w0 = ((const unsigned int*)mask)[0];
    const int mode = (w0 == 0x01010101u) ? 0 : (w0 == 0x3F800000u) ? 2 : 1;

    float vals[8];
    float lmax = -1e30f;
    #pragma unroll
    for (int i = 0; i < 8; i++) {
        size_t f = (size_t)b * S_ + tid + i * 256;
        float sc = 0.f;
        #pragma unroll
        for (int x = 0; x < NTILES; x++) sc += g_part[(size_t)x * M_ + f];
        bool alive;
        if (mode == 0)      alive = ((const unsigned char*)mask)[f] != 0;
        else if (mode == 1) alive = ((const int*)mask)[f] != 0;
        else                alive = ((const float*)mask)[f] != 0.0f;
        if (!alive) sc = -1e9f;
        vals[i] = sc;
        lmax = fmaxf(lmax, sc);
    }
    float m = lmax;
    #pragma unroll
    for (int off = 16; off; off >>= 1)
        m = fmaxf(m, __shfl_xor_sync(0xffffffffu, m, off));
    if ((tid & 31) == 0) red[tid >> 5] = m;
    __syncthreads();
    float bm = red[0];
    #pragma unroll
    for (int i = 1; i < 8; i++) bm = fmaxf(bm, red[i]);

    float lsum = 0.f;
    #pragma unroll
    for (int i = 0; i < 8; i++) {
        vals[i] = expf(vals[i] - bm);
        lsum += vals[i];
    }
    #pragma unroll
    for (int off = 16; off; off >>= 1)
        lsum += __shfl_xor_sync(0xffffffffu, lsum, off);
    __syncthreads();
    if ((tid & 31) == 0) red[tid >> 5] = lsum;
    __syncthreads();
    float tot = 0.f;
    #pragma unroll
    for (int i = 0; i < 8; i++) tot += red[i];
    float inv = 1.f / tot;

    #pragma unroll
    for (int i = 0; i < 8; i++)
        attn[(size_t)b * S_ + tid + i * 256] = vals[i] * inv;
}

// ---------------------------------------------------------------------------
// context from fp16 enc copy (halved read traffic).
// ---------------------------------------------------------------------------
__global__ void context_kernel(const float* __restrict__ attn,
                               float* __restrict__ ctx) {
    const int b  = blockIdx.x;
    const int h  = blockIdx.y * 128 + (threadIdx.x & 127);
    const int sp = threadIdx.x >> 7;
    const __half* e = g_ench + (size_t)b * S_ * H_ + h;
    const float* w = attn + (size_t)b * S_;
    float acc = 0.f;
    #pragma unroll 8
    for (int s = sp; s < S_; s += 2)
        acc = fmaf(w[s], __half2float(e[(size_t)s * H_]), acc);
    __shared__ float sh[256];
    sh[threadIdx.x] = acc;
    __syncthreads();
    if (threadIdx.x < 128)
        ctx[(size_t)b * H_ + h] = sh[threadIdx.x] + sh[threadIdx.x + 128];
}

// ---------------------------------------------------------------------------
extern "C" void kernel_launch(void* const* d_in, const int* in_sizes, int n_in,
                              void* d_out, int out_size) {
    (void)in_sizes; (void)n_in; (void)out_size;
    const float* dec  = (const float*)d_in[0];
    const float* enc  = (const float*)d_in[1];
    const void*  mask = (const void*)d_in[2];
    const float* Wenc = (const float*)d_in[3];
    const float* Wdec = (const float*)d_in[4];
    const float* v    = (const float*)d_in[5];
    float* out  = (float*)d_out;
    float* attn = out + (size_t)B_ * H_;

    cudaFuncSetAttribute(fused_score_kernel,
                         cudaFuncAttributeMaxDynamicSharedMemorySize, DYN_BYTES);

    cvt_enc_kernel<<<65536, 256>>>(enc);
    cvt_w_kernel<<<512, 256>>>(Wenc);
    dec_proj_kernel<<<2048, 256>>>(dec, Wdec);
    dim3 g2(NTILES, M_ / MT);                 // (8, 512), x fastest -> L2 reuse
    fused_score_kernel<<<g2, 256, DYN_BYTES>>>(v);
    softmax_kernel<<<B_, 256>>>(mask, attn);
    context_kernel<<<dim3(B_, H_ / 128), 256>>>(attn, out);
}

// round 11
// speedup vs baseline: 2.2571x; 1.0015x over previous
#include <cuda_runtime.h>
#include <cuda_fp16.h>
#include <cstdint>
#include <math.h>

#define B_ 64
#define S_ 2048
#define H_ 1024
#define M_ (B_*S_)
#define NTILES 8          // H_/128 N-blocks
#define KT 64             // k elems per tile
#define K_ITERS (H_/KT)   // 16
#define RS 144            // smem row stride bytes (128B data + 16 pad)
#define MT 256            // CTA tile M
#define NT 128            // CTA tile N
#define ASTG (MT*RS)      // 36864
#define BSTG (NT*RS)      // 18432
#define STG  (ASTG+BSTG)  // 55296
#define NSTG 3
#define DYN_BYTES (NSTG*STG)   // 165888

__device__ float  g_dp[B_ * H_];
__device__ float  g_part[NTILES * M_];
__device__ __half g_ench[(size_t)M_ * H_];   // 256 MB fp16 copy of enc
__device__ __half g_wh[(size_t)H_ * H_];     // 2 MB fp16 copy of W_enc

__device__ __forceinline__ uint32_t smem_u32(const void* p) {
    uint32_t a;
    asm("{ .reg .u64 t; cvta.to.shared.u64 t, %1; cvt.u32.u64 %0, t; }" : "=r"(a) : "l"(p));
    return a;
}
__device__ __forceinline__ void cp_async16(uint32_t dst, const void* src) {
    asm volatile("cp.async.cg.shared.global [%0], [%1], 16;" :: "r"(dst), "l"(src));
}
__device__ __forceinline__ void ldsm_x4(uint32_t r[4], uint32_t addr) {
    asm volatile("ldmatrix.sync.aligned.m8n8.x4.shared.b16 {%0,%1,%2,%3}, [%4];"
                 : "=r"(r[0]), "=r"(r[1]), "=r"(r[2]), "=r"(r[3]) : "r"(addr));
}
__device__ __forceinline__ void mma_f16(float c[4], const uint32_t a[4],
                                        uint32_t b0, uint32_t b1) {
    asm volatile(
        "mma.sync.aligned.m16n8k16.row.col.f32.f16.f16.f32 "
        "{%0,%1,%2,%3}, {%4,%5,%6,%7}, {%8,%9}, {%0,%1,%2,%3};"
        : "+f"(c[0]), "+f"(c[1]), "+f"(c[2]), "+f"(c[3])
        : "r"(a[0]), "r"(a[1]), "r"(a[2]), "r"(a[3]), "r"(b0), "r"(b1));
}
__device__ __forceinline__ float fast_tanh(float x) {
    float y; asm("tanh.approx.f32 %0, %1;" : "=f"(y) : "f"(x)); return y;
}

// ---------------------------------------------------------------------------
__global__ void cvt_enc_kernel(const float* __restrict__ src) {
    size_t c = (size_t)blockIdx.x * blockDim.x + threadIdx.x;
    const float4* s = (const float4*)src + c * 2;
    float4 a = s[0], b = s[1];
    __half2 h[4];
    h[0] = __floats2half2_rn(a.x, a.y);
    h[1] = __floats2half2_rn(a.z, a.w);
    h[2] = __floats2half2_rn(b.x, b.y);
    h[3] = __floats2half2_rn(b.z, b.w);
    *((uint4*)g_ench + c) = *(uint4*)h;
}
__global__ void cvt_w_kernel(const float* __restrict__ src) {
    size_t c = (size_t)blockIdx.x * blockDim.x + threadIdx.x;
    const float4* s = (const float4*)src + c * 2;
    float4 a = s[0], b = s[1];
    __half2 h[4];
    h[0] = __floats2half2_rn(a.x, a.y);
    h[1] = __floats2half2_rn(a.z, a.w);
    h[2] = __floats2half2_rn(b.x, b.y);
    h[3] = __floats2half2_rn(b.z, b.w);
    *((uint4*)g_wh + c) = *(uint4*)h;
}

// ---------------------------------------------------------------------------
__global__ void dec_proj_kernel(const float* __restrict__ dec,
                                const float* __restrict__ Wdec) {
    int wid  = (blockIdx.x * blockDim.x + threadIdx.x) >> 5;
    int lane = threadIdx.x & 31;
    int o  = wid >> 4;
    int b0 = (wid & 15) * 4;
    const float* wr = Wdec + (size_t)o * H_;
    const float* d0 = dec + (size_t)(b0 + 0) * H_;
    const float* d1 = dec + (size_t)(b0 + 1) * H_;
    const float* d2 = dec + (size_t)(b0 + 2) * H_;
    const float* d3 = dec + (size_t)(b0 + 3) * H_;
    float a0 = 0.f, a1 = 0.f, a2 = 0.f, a3 = 0.f;
    #pragma unroll 4
    for (int h = lane; h < H_; h += 32) {
        float w = wr[h];
        a0 = fmaf(w, d0[h], a0);
        a1 = fmaf(w, d1[h], a1);
        a2 = fmaf(w, d2[h], a2);
        a3 = fmaf(w, d3[h], a3);
    }
    #pragma unroll
    for (int off = 16; off; off >>= 1) {
        a0 += __shfl_down_sync(0xffffffffu, a0, off);
        a1 += __shfl_down_sync(0xffffffffu, a1, off);
        a2 += __shfl_down_sync(0xffffffffu, a2, off);
        a3 += __shfl_down_sync(0xffffffffu, a3, off);
    }
    if (lane == 0) {
        g_dp[(size_t)(b0 + 0) * H_ + o] = a0;
        g_dp[(size_t)(b0 + 1) * H_ + o] = a1;
        g_dp[(size_t)(b0 + 2) * H_ + o] = a2;
        g_dp[(size_t)(b0 + 3) * H_ + o] = a3;
    }
}

// ---------------------------------------------------------------------------
// Fused fp16 MMA GEMM (encH @ WencH^T) + tanh(.+dec_proj).v partial reduction.
// CTA tile 256(M)x128(N), k-tile 64; 8 warps = 4(M)x2(N), warp tile 64x64;
// cp.async 3-stage ring (166 KB dynamic smem); f32 accumulators.
// ---------------------------------------------------------------------------
__global__ void __launch_bounds__(256, 1)
fused_score_kernel(const float* __restrict__ v) {
    extern __shared__ __align__(16) char dynsm[];
    __shared__ float dp_sh[NT];
    __shared__ float v_sh[NT];
    __shared__ float part_sh[2][MT];

    const int tid   = threadIdx.x;
    const int lane  = tid & 31;
    const int warp  = tid >> 5;
    const int warpM = warp & 3;     // 0..3
    const int warpN = warp >> 2;    // 0..1
    const int g = lane >> 2;
    const int t = lane & 3;

    const int nBase = blockIdx.x * NT;
    const int mBase = blockIdx.y * MT;
    const int b     = mBase >> 11;  // 256 | 2048 -> single batch per tile

    if (tid < NT) {
        dp_sh[tid] = g_dp[(size_t)b * H_ + nBase + tid];
        v_sh[tid]  = v[nBase + tid];
    }

    const uint32_t sm0 = smem_u32(dynsm);
    const __half* encH = g_ench;
    const __half* wH   = g_wh;

    float acc[4][8][4];
    #pragma unroll
    for (int mi = 0; mi < 4; mi++)
        #pragma unroll
        for (int ni = 0; ni < 8; ni++)
            #pragma unroll
            for (int c = 0; c < 4; c++) acc[mi][ni][c] = 0.f;

    // cp.async per ktile(64): A = 2048 chunks (16B), B = 1024; 256 threads.
#define ISSUE(J) {                                                          \
    const uint32_t sa_ = sm0 + ((J) % NSTG) * STG;                          \
    const uint32_t sb_ = sa_ + ASTG;                                        \
    const size_t ko_ = (size_t)(J) * KT;                                    \
    _Pragma("unroll")                                                       \
    for (int i_ = 0; i_ < 8; i_++) {                                        \
        int c_ = tid + (i_ << 8);                                           \
        int r_ = c_ >> 3, q_ = c_ & 7;                                      \
        cp_async16(sa_ + r_ * RS + q_ * 16,                                 \
                   encH + (size_t)(mBase + r_) * H_ + ko_ + q_ * 8);        \
    }                                                                       \
    _Pragma("unroll")                                                       \
    for (int i_ = 0; i_ < 4; i_++) {                                        \
        int c_ = tid + (i_ << 8);                                           \
        int r_ = c_ >> 3, q_ = c_ & 7;                                      \
        cp_async16(sb_ + r_ * RS + q_ * 16,                                 \
                   wH + (size_t)(nBase + r_) * H_ + ko_ + q_ * 8);          \
    } }

    // ldmatrix per-lane address components
    const int aRow = warpM * 64 + (lane & 7) + ((lane >> 3) & 1) * 8;
    const int aCol = ((lane >> 4) & 1) * 16;
    const int bRow = warpN * 64 + (lane >> 4) * 8 + (lane & 7);
    const int bCol = ((lane >> 3) & 1) * 16;

#define COMPUTE(BUF) {                                                     \
    const uint32_t Ab = sm0 + (BUF) * STG;                                  \
    const uint32_t Bb = Ab + ASTG;                                          \
    _Pragma("unroll")                                                       \
    for (int ks = 0; ks < 4; ks++) {                                        \
        uint32_t af[4][4], bf[4][4];                                        \
        _Pragma("unroll")                                                   \
        for (int mi = 0; mi < 4; mi++)                                      \
            ldsm_x4(af[mi], Ab + (aRow + mi * 16) * RS + ks * 32 + aCol);   \
        _Pragma("unroll")                                                   \
        for (int nj = 0; nj < 4; nj++)                                      \
            ldsm_x4(bf[nj], Bb + (bRow + nj * 16) * RS + ks * 32 + bCol);   \
        _Pragma("unroll")                                                   \
        for (int mi = 0; mi < 4; mi++) {                                    \
            _Pragma("unroll")                                               \
            for (int nj = 0; nj < 4; nj++) {                                \
                mma_f16(acc[mi][2*nj],   af[mi], bf[nj][0], bf[nj][1]);     \
                mma_f16(acc[mi][2*nj+1], af[mi], bf[nj][2], bf[nj][3]);     \
            }                                                               \
        }                                                                   \
    } }

    // prologue: 2 stages in flight
    ISSUE(0); asm volatile("cp.async.commit_group;");
    ISSUE(1); asm volatile("cp.async.commit_group;");

    #pragma unroll 1
    for (int kt = 0; kt < K_ITERS; kt++) {
        asm volatile("cp.async.wait_group 1;");
        __syncthreads();
        COMPUTE(kt % NSTG);
        if (kt + 2 < K_ITERS) ISSUE(kt + 2);
        asm volatile("cp.async.commit_group;");
    }
#undef ISSUE
#undef COMPUTE

    // Epilogue: energy = tanh(acc + dec_proj), partial = sum_col energy * v
    float rs[8];
    #pragma unroll
    for (int i = 0; i < 8; i++) rs[i] = 0.f;

    #pragma unroll
    for (int mi = 0; mi < 4; mi++) {
        #pragma unroll
        for (int ni = 0; ni < 8; ni++) {
            int c0 = warpN * 64 + ni * 8 + 2 * t;
            float d0 = dp_sh[c0],     d1 = dp_sh[c0 + 1];
            float w0 = v_sh[c0],      w1 = v_sh[c0 + 1];
            rs[2 * mi]     += fast_tanh(acc[mi][ni][0] + d0) * w0
                            + fast_tanh(acc[mi][ni][1] + d1) * w1;
            rs[2 * mi + 1] += fast_tanh(acc[mi][ni][2] + d0) * w0
                            + fast_tanh(acc[mi][ni][3] + d1) * w1;
        }
    }
    #pragma unroll
    for (int i = 0; i < 8; i++) {
        rs[i] += __shfl_xor_sync(0xffffffffu, rs[i], 1);
        rs[i] += __shfl_xor_sync(0xffffffffu, rs[i], 2);
    }
    if (t == 0) {
        #pragma unroll
        for (int mi = 0; mi < 4; mi++) {
            part_sh[warpN][warpM * 64 + mi * 16 + g]     = rs[2 * mi];
            part_sh[warpN][warpM * 64 + mi * 16 + g + 8] = rs[2 * mi + 1];
        }
    }
    __syncthreads();
    {
        float sres = part_sh[0][tid] + part_sh[1][tid];
        g_part[(size_t)blockIdx.x * M_ + mBase + tid] = sres;
    }
}

// ---------------------------------------------------------------------------
// Softmax; mask dtype sniffed inline from word 0 (uint8 / int32 / float32).
// ---------------------------------------------------------------------------
__global__ void softmax_kernel(const void* __restrict__ mask,
                               float* __restrict__ attn) {
    const int b   = blockIdx.x;
    const int tid = threadIdx.x;  // 256
    __shared__ float red[8];

    unsigned w0 = ((const unsigned int*)mask)[0];
    const int mode = (w0 == 0x01010101u) ? 0 : (w0 == 0x3F800000u) ? 2 : 1;

    float vals[8];
    float lmax = -1e30f;
    #pragma unroll
    for (int i = 0; i < 8; i++) {
        size_t f = (size_t)b * S_ + tid + i * 256;
        float sc = 0.f;
        #pragma unroll
        for (int x = 0; x < NTILES; x++) sc += g_part[(size_t)x * M_ + f];
        bool alive;
        if (mode == 0)      alive = ((const unsigned char*)mask)[f] != 0;
        else if (mode == 1) alive = ((const int*)mask)[f] != 0;
        else                alive = ((const float*)mask)[f] != 0.0f;
        if (!alive) sc = -1e9f;
        vals[i] = sc;
        lmax = fmaxf(lmax, sc);
    }
    float m = lmax;
    #pragma unroll
    for (int off = 16; off; off >>= 1)
        m = fmaxf(m, __shfl_xor_sync(0xffffffffu, m, off));
    if ((tid & 31) == 0) red[tid >> 5] = m;
    __syncthreads();
    float bm = red[0];
    #pragma unroll
    for (int i = 1; i < 8; i++) bm = fmaxf(bm, red[i]);

    float lsum = 0.f;
    #pragma unroll
    for (int i = 0; i < 8; i++) {
        vals[i] = expf(vals[i] - bm);
        lsum += vals[i];
    }
    #pragma unroll
    for (int off = 16; off; off >>= 1)
        lsum += __shfl_xor_sync(0xffffffffu, lsum, off);
    __syncthreads();
    if ((tid & 31) == 0) red[tid >> 5] = lsum;
    __syncthreads();
    float tot = 0.f;
    #pragma unroll
    for (int i = 0; i < 8; i++) tot += red[i];
    float inv = 1.f / tot;

    #pragma unroll
    for (int i = 0; i < 8; i++)
        attn[(size_t)b * S_ + tid + i * 256] = vals[i] * inv;
}

// ---------------------------------------------------------------------------
// context from fp16 enc copy (halved read traffic).
// ---------------------------------------------------------------------------
__global__ void context_kernel(const float* __restrict__ attn,
                               float* __restrict__ ctx) {
    const int b  = blockIdx.x;
    const int h  = blockIdx.y * 128 + (threadIdx.x & 127);
    const int sp = threadIdx.x >> 7;
    const __half* e = g_ench + (size_t)b * S_ * H_ + h;
    const float* w = attn + (size_t)b * S_;
    float acc = 0.f;
    #pragma unroll 8
    for (int s = sp; s < S_; s += 2)
        acc = fmaf(w[s], __half2float(e[(size_t)s * H_]), acc);
    __shared__ float sh[256];
    sh[threadIdx.x] = acc;
    __syncthreads();
    if (threadIdx.x < 128)
        ctx[(size_t)b * H_ + h] = sh[threadIdx.x] + sh[threadIdx.x + 128];
}

// ---------------------------------------------------------------------------
extern "C" void kernel_launch(void* const* d_in, const int* in_sizes, int n_in,
                              void* d_out, int out_size) {
    (void)in_sizes; (void)n_in; (void)out_size;
    const float* dec  = (const float*)d_in[0];
    const float* enc  = (const float*)d_in[1];
    const void*  mask = (const void*)d_in[2];
    const float* Wenc = (const float*)d_in[3];
    const float* Wdec = (const float*)d_in[4];
    const float* v    = (const float*)d_in[5];
    float* out  = (float*)d_out;
    float* attn = out + (size_t)B_ * H_;

    cudaFuncSetAttribute(fused_score_kernel,
                         cudaFuncAttributeMaxDynamicSharedMemorySize, DYN_BYTES);

    cvt_enc_kernel<<<65536, 256>>>(enc);
    cvt_w_kernel<<<512, 256>>>(Wenc);
    dec_proj_kernel<<<2048, 256>>>(dec, Wdec);
    dim3 g2(NTILES, M_ / MT);                 // (8, 512), x fastest -> L2 reuse
    fused_score_kernel<<<g2, 256, DYN_BYTES>>>(v);
    softmax_kernel<<<B_, 256>>>(mask, attn);
    context_kernel<<<dim3(B_, H_ / 128), 256>>>(attn, out);
}

// round 12
// speedup vs baseline: 2.2585x; 1.0006x over previous
#include <cuda_runtime.h>
#include <cuda_fp16.h>
#include <cstdint>
#include <math.h>

#define B_ 64
#define S_ 2048
#define H_ 1024
#define M_ (B_*S_)
#define NTILES 8          // H_/128 N-blocks
#define KT 64             // k elems per tile
#define K_ITERS (H_/KT)   // 16
#define RS 144            // smem row stride bytes (128B data + 16 pad)
#define MT 256            // CTA tile M
#define NT 128            // CTA tile N
#define ASTG (MT*RS)      // 36864
#define BSTG (NT*RS)      // 18432
#define STG  (ASTG+BSTG)  // 55296
#define NSTG 3
#define DYN_BYTES (NSTG*STG)   // 165888

__device__ float  g_dp[B_ * H_];
__device__ float  g_part[NTILES * M_];
__device__ __half g_ench[(size_t)M_ * H_];   // 256 MB fp16 copy of enc
__device__ __half g_wh[(size_t)H_ * H_];     // 2 MB fp16 copy of W_enc

__device__ __forceinline__ uint32_t smem_u32(const void* p) {
    uint32_t a;
    asm("{ .reg .u64 t; cvta.to.shared.u64 t, %1; cvt.u32.u64 %0, t; }" : "=r"(a) : "l"(p));
    return a;
}
__device__ __forceinline__ void cp_async16(uint32_t dst, const void* src) {
    asm volatile("cp.async.cg.shared.global [%0], [%1], 16;" :: "r"(dst), "l"(src));
}
__device__ __forceinline__ void ldsm_x4(uint32_t r[4], uint32_t addr) {
    asm volatile("ldmatrix.sync.aligned.m8n8.x4.shared.b16 {%0,%1,%2,%3}, [%4];"
                 : "=r"(r[0]), "=r"(r[1]), "=r"(r[2]), "=r"(r[3]) : "r"(addr));
}
__device__ __forceinline__ void mma_f16(float c[4], const uint32_t a[4],
                                        uint32_t b0, uint32_t b1) {
    asm volatile(
        "mma.sync.aligned.m16n8k16.row.col.f32.f16.f16.f32 "
        "{%0,%1,%2,%3}, {%4,%5,%6,%7}, {%8,%9}, {%0,%1,%2,%3};"
        : "+f"(c[0]), "+f"(c[1]), "+f"(c[2]), "+f"(c[3])
        : "r"(a[0]), "r"(a[1]), "r"(a[2]), "r"(a[3]), "r"(b0), "r"(b1));
}
__device__ __forceinline__ float fast_tanh(float x) {
    float y; asm("tanh.approx.f32 %0, %1;" : "=f"(y) : "f"(x)); return y;
}

// ---------------------------------------------------------------------------
__global__ void cvt_enc_kernel(const float* __restrict__ src) {
    size_t c = (size_t)blockIdx.x * blockDim.x + threadIdx.x;
    const float4* s = (const float4*)src + c * 2;
    float4 a = s[0], b = s[1];
    __half2 h[4];
    h[0] = __floats2half2_rn(a.x, a.y);
    h[1] = __floats2half2_rn(a.z, a.w);
    h[2] = __floats2half2_rn(b.x, b.y);
    h[3] = __floats2half2_rn(b.z, b.w);
    *((uint4*)g_ench + c) = *(uint4*)h;
}
__global__ void cvt_w_kernel(const float* __restrict__ src) {
    size_t c = (size_t)blockIdx.x * blockDim.x + threadIdx.x;
    const float4* s = (const float4*)src + c * 2;
    float4 a = s[0], b = s[1];
    __half2 h[4];
    h[0] = __floats2half2_rn(a.x, a.y);
    h[1] = __floats2half2_rn(a.z, a.w);
    h[2] = __floats2half2_rn(b.x, b.y);
    h[3] = __floats2half2_rn(b.z, b.w);
    *((uint4*)g_wh + c) = *(uint4*)h;
}

// ---------------------------------------------------------------------------
__global__ void dec_proj_kernel(const float* __restrict__ dec,
                                const float* __restrict__ Wdec) {
    int wid  = (blockIdx.x * blockDim.x + threadIdx.x) >> 5;
    int lane = threadIdx.x & 31;
    int o  = wid >> 4;
    int b0 = (wid & 15) * 4;
    const float* wr = Wdec + (size_t)o * H_;
    const float* d0 = dec + (size_t)(b0 + 0) * H_;
    const float* d1 = dec + (size_t)(b0 + 1) * H_;
    const float* d2 = dec + (size_t)(b0 + 2) * H_;
    const float* d3 = dec + (size_t)(b0 + 3) * H_;
    float a0 = 0.f, a1 = 0.f, a2 = 0.f, a3 = 0.f;
    #pragma unroll 4
    for (int h = lane; h < H_; h += 32) {
        float w = wr[h];
        a0 = fmaf(w, d0[h], a0);
        a1 = fmaf(w, d1[h], a1);
        a2 = fmaf(w, d2[h], a2);
        a3 = fmaf(w, d3[h], a3);
    }
    #pragma unroll
    for (int off = 16; off; off >>= 1) {
        a0 += __shfl_down_sync(0xffffffffu, a0, off);
        a1 += __shfl_down_sync(0xffffffffu, a1, off);
        a2 += __shfl_down_sync(0xffffffffu, a2, off);
        a3 += __shfl_down_sync(0xffffffffu, a3, off);
    }
    if (lane == 0) {
        g_dp[(size_t)(b0 + 0) * H_ + o] = a0;
        g_dp[(size_t)(b0 + 1) * H_ + o] = a1;
        g_dp[(size_t)(b0 + 2) * H_ + o] = a2;
        g_dp[(size_t)(b0 + 3) * H_ + o] = a3;
    }
}

// ---------------------------------------------------------------------------
// Fused fp16 MMA GEMM (encH @ WencH^T) + tanh(.+dec_proj).v partial reduction.
// CTA tile 256(M)x128(N), k-tile 64; 8 warps = 4(M)x2(N), warp tile 64x64;
// cp.async 3-stage ring (166 KB dynamic smem); f32 accumulators.
// ---------------------------------------------------------------------------
__global__ void __launch_bounds__(256, 1)
fused_score_kernel(const float* __restrict__ v) {
    extern __shared__ __align__(16) char dynsm[];
    __shared__ float dp_sh[NT];
    __shared__ float v_sh[NT];
    __shared__ float part_sh[2][MT];

    const int tid   = threadIdx.x;
    const int lane  = tid & 31;
    const int warp  = tid >> 5;
    const int warpM = warp & 3;     // 0..3
    const int warpN = warp >> 2;    // 0..1
    const int g = lane >> 2;
    const int t = lane & 3;

    const int nBase = blockIdx.x * NT;
    const int mBase = blockIdx.y * MT;
    const int b     = mBase >> 11;  // 256 | 2048 -> single batch per tile

    if (tid < NT) {
        dp_sh[tid] = g_dp[(size_t)b * H_ + nBase + tid];
        v_sh[tid]  = v[nBase + tid];
    }

    const uint32_t sm0 = smem_u32(dynsm);
    const __half* encH = g_ench;
    const __half* wH   = g_wh;

    float acc[4][8][4];
    #pragma unroll
    for (int mi = 0; mi < 4; mi++)
        #pragma unroll
        for (int ni = 0; ni < 8; ni++)
            #pragma unroll
            for (int c = 0; c < 4; c++) acc[mi][ni][c] = 0.f;

    // cp.async per ktile(64): A = 2048 chunks (16B), B = 1024; 256 threads.
#define ISSUE(J) {                                                          \
    const uint32_t sa_ = sm0 + ((J) % NSTG) * STG;                          \
    const uint32_t sb_ = sa_ + ASTG;                                        \
    const size_t ko_ = (size_t)(J) * KT;                                    \
    _Pragma("unroll")                                                       \
    for (int i_ = 0; i_ < 8; i_++) {                                        \
        int c_ = tid + (i_ << 8);                                           \
        int r_ = c_ >> 3, q_ = c_ & 7;                                      \
        cp_async16(sa_ + r_ * RS + q_ * 16,                                 \
                   encH + (size_t)(mBase + r_) * H_ + ko_ + q_ * 8);        \
    }                                                                       \
    _Pragma("unroll")                                                       \
    for (int i_ = 0; i_ < 4; i_++) {                                        \
        int c_ = tid + (i_ << 8);                                           \
        int r_ = c_ >> 3, q_ = c_ & 7;                                      \
        cp_async16(sb_ + r_ * RS + q_ * 16,                                 \
                   wH + (size_t)(nBase + r_) * H_ + ko_ + q_ * 8);          \
    } }

    // ldmatrix per-lane address components
    const int aRow = warpM * 64 + (lane & 7) + ((lane >> 3) & 1) * 8;
    const int aCol = ((lane >> 4) & 1) * 16;
    const int bRow = warpN * 64 + (lane >> 4) * 8 + (lane & 7);
    const int bCol = ((lane >> 3) & 1) * 16;

#define COMPUTE(BUF) {                                                     \
    const uint32_t Ab = sm0 + (BUF) * STG;                                  \
    const uint32_t Bb = Ab + ASTG;                                          \
    _Pragma("unroll")                                                       \
    for (int ks = 0; ks < 4; ks++) {                                        \
        uint32_t af[4][4], bf[4][4];                                        \
        _Pragma("unroll")                                                   \
        for (int mi = 0; mi < 4; mi++)                                      \
            ldsm_x4(af[mi], Ab + (aRow + mi * 16) * RS + ks * 32 + aCol);   \
        _Pragma("unroll")                                                   \
        for (int nj = 0; nj < 4; nj++)                                      \
            ldsm_x4(bf[nj], Bb + (bRow + nj * 16) * RS + ks * 32 + bCol);   \
        _Pragma("unroll")                                                   \
        for (int mi = 0; mi < 4; mi++) {                                    \
            _Pragma("unroll")                                               \
            for (int nj = 0; nj < 4; nj++) {                                \
                mma_f16(acc[mi][2*nj],   af[mi], bf[nj][0], bf[nj][1]);     \
                mma_f16(acc[mi][2*nj+1], af[mi], bf[nj][2], bf[nj][3]);     \
            }                                                               \
        }                                                                   \
    } }

    // prologue: 2 stages in flight
    ISSUE(0); asm volatile("cp.async.commit_group;");
    ISSUE(1); asm volatile("cp.async.commit_group;");

    #pragma unroll 1
    for (int kt = 0; kt < K_ITERS; kt++) {
        asm volatile("cp.async.wait_group 1;");
        __syncthreads();
        COMPUTE(kt % NSTG);
        if (kt + 2 < K_ITERS) ISSUE(kt + 2);
        asm volatile("cp.async.commit_group;");
    }
#undef ISSUE
#undef COMPUTE

    // Epilogue: energy = tanh(acc + dec_proj), partial = sum_col energy * v
    float rs[8];
    #pragma unroll
    for (int i = 0; i < 8; i++) rs[i] = 0.f;

    #pragma unroll
    for (int mi = 0; mi < 4; mi++) {
        #pragma unroll
        for (int ni = 0; ni < 8; ni++) {
            int c0 = warpN * 64 + ni * 8 + 2 * t;
            float d0 = dp_sh[c0],     d1 = dp_sh[c0 + 1];
            float w0 = v_sh[c0],      w1 = v_sh[c0 + 1];
            rs[2 * mi]     += fast_tanh(acc[mi][ni][0] + d0) * w0
                            + fast_tanh(acc[mi][ni][1] + d1) * w1;
            rs[2 * mi + 1] += fast_tanh(acc[mi][ni][2] + d0) * w0
                            + fast_tanh(acc[mi][ni][3] + d1) * w1;
        }
    }
    #pragma unroll
    for (int i = 0; i < 8; i++) {
        rs[i] += __shfl_xor_sync(0xffffffffu, rs[i], 1);
        rs[i] += __shfl_xor_sync(0xffffffffu, rs[i], 2);
    }
    if (t == 0) {
        #pragma unroll
        for (int mi = 0; mi < 4; mi++) {
            part_sh[warpN][warpM * 64 + mi * 16 + g]     = rs[2 * mi];
            part_sh[warpN][warpM * 64 + mi * 16 + g + 8] = rs[2 * mi + 1];
        }
    }
    __syncthreads();
    {
        float sres = part_sh[0][tid] + part_sh[1][tid];
        g_part[(size_t)blockIdx.x * M_ + mBase + tid] = sres;
    }
}

// ---------------------------------------------------------------------------
// Softmax; mask dtype sniffed inline from word 0 (uint8 / int32 / float32).
// ---------------------------------------------------------------------------
__global__ void softmax_kernel(const void* __restrict__ mask,
                               float* __restrict__ attn) {
    const int b   = blockIdx.x;
    const int tid = threadIdx.x;  // 256
    __shared__ float red[8];

    unsigned w0 = ((const unsigned int*)mask)[0];
    const int mode = (w0 == 0x01010101u) ? 0 : (w0 == 0x3F800000u) ? 2 : 1;

    float vals[8];
    float lmax = -1e30f;
    #pragma unroll
    for (int i = 0; i < 8; i++) {
        size_t f = (size_t)b * S_ + tid + i * 256;
        float sc = 0.f;
        #pragma unroll
        for (int x = 0; x < NTILES; x++) sc += g_part[(size_t)x * M_ + f];
        bool alive;
        if (mode == 0)      alive = ((const unsigned char*)mask)[f] != 0;
        else if (mode == 1) alive = ((const int*)mask)[f] != 0;
        else                alive = ((const float*)mask)[f] != 0.0f;
        if (!alive) sc = -1e9f;
        vals[i] = sc;
        lmax = fmaxf(lmax, sc);
    }
    float m = lmax;
    #pragma unroll
    for (int off = 16; off; off >>= 1)
        m = fmaxf(m, __shfl_xor_sync(0xffffffffu, m, off));
    if ((tid & 31) == 0) red[tid >> 5] = m;
    __syncthreads();
    float bm = red[0];
    #pragma unroll
    for (int i = 1; i < 8; i++) bm = fmaxf(bm, red[i]);

    float lsum = 0.f;
    #pragma unroll
    for (int i = 0; i < 8; i++) {
        vals[i] = expf(vals[i] - bm);
        lsum += vals[i];
    }
    #pragma unroll
    for (int off = 16; off; off >>= 1)
        lsum += __shfl_xor_sync(0xffffffffu, lsum, off);
    __syncthreads();
    if ((tid & 31) == 0) red[tid >> 5] = lsum;
    __syncthreads();
    float tot = 0.f;
    #pragma unroll
    for (int i = 0; i < 8; i++) tot += red[i];
    float inv = 1.f / tot;

    #pragma unroll
    for (int i = 0; i < 8; i++)
        attn[(size_t)b * S_ + tid + i * 256] = vals[i] * inv;
}

// ---------------------------------------------------------------------------
// context from fp16 enc copy (halved read traffic).
// ---------------------------------------------------------------------------
__global__ void context_kernel(const float* __restrict__ attn,
                               float* __restrict__ ctx) {
    const int b  = blockIdx.x;
    const int h  = blockIdx.y * 128 + (threadIdx.x & 127);
    const int sp = threadIdx.x >> 7;
    const __half* e = g_ench + (size_t)b * S_ * H_ + h;
    const float* w = attn + (size_t)b * S_;
    float acc = 0.f;
    #pragma unroll 8
    for (int s = sp; s < S_; s += 2)
        acc = fmaf(w[s], __half2float(e[(size_t)s * H_]), acc);
    __shared__ float sh[256];
    sh[threadIdx.x] = acc;
    __syncthreads();
    if (threadIdx.x < 128)
        ctx[(size_t)b * H_ + h] = sh[threadIdx.x] + sh[threadIdx.x + 128];
}

// ---------------------------------------------------------------------------
extern "C" void kernel_launch(void* const* d_in, const int* in_sizes, int n_in,
                              void* d_out, int out_size) {
    (void)in_sizes; (void)n_in; (void)out_size;
    const float* dec  = (const float*)d_in[0];
    const float* enc  = (const float*)d_in[1];
    const void*  mask = (const void*)d_in[2];
    const float* Wenc = (const float*)d_in[3];
    const float* Wdec = (const float*)d_in[4];
    const float* v    = (const float*)d_in[5];
    float* out  = (float*)d_out;
    float* attn = out + (size_t)B_ * H_;

    cudaFuncSetAttribute(fused_score_kernel,
                         cudaFuncAttributeMaxDynamicSharedMemorySize, DYN_BYTES);

    cvt_enc_kernel<<<65536, 256>>>(enc);
    cvt_w_kernel<<<512, 256>>>(Wenc);
    dec_proj_kernel<<<2048, 256>>>(dec, Wdec);
    dim3 g2(NTILES, M_ / MT);                 // (8, 512), x fastest -> L2 reuse
    fused_score_kernel<<<g2, 256, DYN_BYTES>>>(v);
    softmax_kernel<<<B_, 256>>>(mask, attn);
    context_kernel<<<dim3(B_, H_ / 128), 256>>>(attn, out);
}